// round 2
// baseline (speedup 1.0000x reference)
#include <cuda_runtime.h>

// ---------------------------------------------------------------------------
// HiLo attention, b=8, dim=256, H=W=64, WS=2, 4+4 heads, head_dim=32
// Round 1: fp32 baseline resubmit (R0 never ran: broker container failure).
// 8 kernels, device-global scratch (no allocations).
// ---------------------------------------------------------------------------

#define BB 8
#define CDIM 256
#define HWDIM 64
#define NTOK 4096          // 64*64 tokens per batch
#define MPOOL 1024         // 32*32 pooled tokens per batch
#define NHEADS 4
#define HD 32
#define ATTN_SCALE 0.17677669529663687f   // 32^-0.5

// scratch (static device globals are allowed; ~117 MB total)
__device__ float g_qkv [BB * NTOK * 384];   // hifi qkv  [b][t][s*128+head*32+d]
__device__ float g_ql  [BB * NTOK * 128];   // lofi q    [b][t][head*32+d]
__device__ float g_pool[BB * CDIM * MPOOL]; // pooled    [b][c][m]  (K-major for GEMM)
__device__ float g_kvl [BB * MPOOL * 256];  // lofi kv   [b][m][s*128+head*32+d]
__device__ float g_oh  [BB * NTOK * 128];   // hifi attn out
__device__ float g_ol  [BB * NTOK * 128];   // lofi attn out

// ---------------------------------------------------------------------------
// GEMM with A stored transposed in memory: C[b][m][n] = sum_k A[b][k][m]*W[k][n]
// K = 256 fixed. BM=BN=64, BK=16, 256 threads, 4x4 per thread.
// ---------------------------------------------------------------------------
__global__ __launch_bounds__(256) void gemm_xt(
    const float* __restrict__ A, long aBatch,
    const float* __restrict__ W,
    float* __restrict__ Cout, long cBatch,
    int M, int N)
{
    __shared__ float As[16][64];
    __shared__ float Ws[16][64];

    const int tid = threadIdx.x;
    const int tx = tid & 15;       // -> n
    const int ty = tid >> 4;       // -> m
    const int m0 = blockIdx.x * 64;
    const int n0 = blockIdx.y * 64;
    const float* Ab = A + (long)blockIdx.z * aBatch;
    float* Cb = Cout + (long)blockIdx.z * cBatch;

    const int lk = tid >> 4;           // 0..15 (k within tile)
    const int lm = (tid & 15) * 4;     // 0..60

    float acc[4][4] = {};

    for (int k0 = 0; k0 < 256; k0 += 16) {
        float4 av = *(const float4*)&Ab[(long)(k0 + lk) * M + m0 + lm];
        float4 wv = *(const float4*)&W[(long)(k0 + lk) * N + n0 + lm];
        __syncthreads();
        *(float4*)&As[lk][lm] = av;
        *(float4*)&Ws[lk][lm] = wv;
        __syncthreads();
#pragma unroll
        for (int kk = 0; kk < 16; kk++) {
            float4 a4 = *(const float4*)&As[kk][ty * 4];
            float4 w4 = *(const float4*)&Ws[kk][tx * 4];
            float a[4] = {a4.x, a4.y, a4.z, a4.w};
            float w[4] = {w4.x, w4.y, w4.z, w4.w};
#pragma unroll
            for (int i = 0; i < 4; i++)
#pragma unroll
                for (int j = 0; j < 4; j++)
                    acc[i][j] += a[i] * w[j];
        }
    }
#pragma unroll
    for (int i = 0; i < 4; i++) {
        float4 r = make_float4(acc[i][0], acc[i][1], acc[i][2], acc[i][3]);
        *(float4*)&Cb[(long)(m0 + ty * 4 + i) * N + n0 + tx * 4] = r;
    }
}

// ---------------------------------------------------------------------------
// 2x2 average pool, reading x [b][c][64][64] -> g_pool [b][c][1024]
// ---------------------------------------------------------------------------
__global__ __launch_bounds__(256) void pool_kernel(const float* __restrict__ x)
{
    const int bc = blockIdx.x;                 // b*256 + c
    const float* xp = x + (long)bc * 4096;
    float* pp = g_pool + (long)bc * 1024;
    for (int m = threadIdx.x; m < 1024; m += 256) {
        const int hg = m >> 5, wg = m & 31;
        const float* r0 = xp + (hg * 2) * 64 + wg * 2;
        pp[m] = 0.25f * (r0[0] + r0[1] + r0[64] + r0[65]);
    }
}

// ---------------------------------------------------------------------------
// hifi window attention: one warp per (b, window, head). lane = head dim.
// ---------------------------------------------------------------------------
__global__ __launch_bounds__(256) void hifi_attn()
{
    const int wid = (blockIdx.x * blockDim.x + threadIdx.x) >> 5;
    const int lane = threadIdx.x & 31;
    const int head = wid & 3;
    const int win = (wid >> 2) & 1023;
    const int b = wid >> 12;
    const int hg = win >> 5, wgc = win & 31;

    float q[4], k[4], v[4];
    int t[4];
#pragma unroll
    for (int i = 0; i < 4; i++) {
        const int r = 2 * hg + (i >> 1);
        const int c = 2 * wgc + (i & 1);
        t[i] = r * 64 + c;
        const float* base = g_qkv + (long)(b * NTOK + t[i]) * 384 + head * 32 + lane;
        q[i] = base[0];
        k[i] = base[128];
        v[i] = base[256];
    }
    float s[4][4];
#pragma unroll
    for (int i = 0; i < 4; i++)
#pragma unroll
        for (int j = 0; j < 4; j++) {
            float p = q[i] * k[j];
#pragma unroll
            for (int off = 16; off; off >>= 1)
                p += __shfl_xor_sync(0xffffffffu, p, off);
            s[i][j] = p * ATTN_SCALE;
        }
#pragma unroll
    for (int i = 0; i < 4; i++) {
        float mx = fmaxf(fmaxf(s[i][0], s[i][1]), fmaxf(s[i][2], s[i][3]));
        float e0 = __expf(s[i][0] - mx);
        float e1 = __expf(s[i][1] - mx);
        float e2 = __expf(s[i][2] - mx);
        float e3 = __expf(s[i][3] - mx);
        float inv = 1.0f / (e0 + e1 + e2 + e3);
        float o = (e0 * v[0] + e1 * v[1] + e2 * v[2] + e3 * v[3]) * inv;
        g_oh[(long)(b * NTOK + t[i]) * 128 + head * 32 + lane] = o;
    }
}

// ---------------------------------------------------------------------------
// lofi attention (flash-style): block = 256 thr = 8 warps; each warp owns 32
// q-rows (lane = row). KV streamed in 32-row chunks through SMEM; every LDS in
// the hot loop is a warp-broadcast, so the loop is pure FMA-pipe work.
// ---------------------------------------------------------------------------
__global__ __launch_bounds__(256, 2) void lofi_attn()
{
    __shared__ float ks[32][32];
    __shared__ float vs[32][32];

    const int tid = threadIdx.x;
    const int lane = tid & 31;
    const int warp = tid >> 5;
    const int bh = blockIdx.y;            // 0..31
    const int b = bh >> 2, head = bh & 3;
    const int t = blockIdx.x * 256 + warp * 32 + lane;

    const float* qp = g_ql + (long)(b * NTOK + t) * 128 + head * 32;
    float q[32], o[32];
#pragma unroll
    for (int d = 0; d < 32; d += 4) {
        float4 v4 = *(const float4*)&qp[d];
        q[d] = v4.x; q[d + 1] = v4.y; q[d + 2] = v4.z; q[d + 3] = v4.w;
        o[d] = 0.f; o[d + 1] = 0.f; o[d + 2] = 0.f; o[d + 3] = 0.f;
    }
    float mrun = -1e30f, lsum = 0.f;

    const float* kvb = g_kvl + (long)b * MPOOL * 256 + head * 32;
    const int lj = tid >> 3;            // 0..31 (kv row in chunk)
    const int ld = (tid & 7) * 4;       // 0..28

    for (int j0 = 0; j0 < MPOOL; j0 += 32) {
        __syncthreads();
        {
            const float* row = kvb + (long)(j0 + lj) * 256;
            *(float4*)&ks[lj][ld] = *(const float4*)&row[ld];
            *(float4*)&vs[lj][ld] = *(const float4*)&row[128 + ld];
        }
        __syncthreads();

        float s[32];
#pragma unroll
        for (int j = 0; j < 32; j++) {
            float acc = 0.f;
#pragma unroll
            for (int d = 0; d < 32; d += 4) {
                float4 k4 = *(const float4*)&ks[j][d];
                acc += q[d] * k4.x + q[d + 1] * k4.y + q[d + 2] * k4.z + q[d + 3] * k4.w;
            }
            s[j] = acc * ATTN_SCALE;
        }
        float cmax = s[0];
#pragma unroll
        for (int j = 1; j < 32; j++) cmax = fmaxf(cmax, s[j]);
        const float mnew = fmaxf(mrun, cmax);
        const float sf = __expf(mrun - mnew);
        mrun = mnew;
        lsum *= sf;
#pragma unroll
        for (int d = 0; d < 32; d++) o[d] *= sf;
#pragma unroll
        for (int j = 0; j < 32; j++) { s[j] = __expf(s[j] - mnew); lsum += s[j]; }
#pragma unroll
        for (int j = 0; j < 32; j++) {
#pragma unroll
            for (int d = 0; d < 32; d += 4) {
                float4 v4 = *(const float4*)&vs[j][d];
                o[d]     += s[j] * v4.x;
                o[d + 1] += s[j] * v4.y;
                o[d + 2] += s[j] * v4.z;
                o[d + 3] += s[j] * v4.w;
            }
        }
    }
    const float inv = 1.0f / lsum;
    float* op = g_ol + (long)(b * NTOK + t) * 128 + head * 32;
#pragma unroll
    for (int d = 0; d < 32; d += 4) {
        *(float4*)&op[d] = make_float4(o[d] * inv, o[d + 1] * inv,
                                       o[d + 2] * inv, o[d + 3] * inv);
    }
}

// ---------------------------------------------------------------------------
// Projection GEMM: out[(b*256 + coff + n)*4096 + m] = bias[n] + sum_k A[b][m][k]*W[k][n]
// A row-major [M][128]. Writes straight into the chw-layout output (fused concat
// + transpose), coalesced along m.
// ---------------------------------------------------------------------------
__global__ __launch_bounds__(256) void gemm_proj(
    const float* __restrict__ A, long aBatch,
    const float* __restrict__ W,
    const float* __restrict__ bias,
    float* __restrict__ out, int coff)
{
    __shared__ float As[16][68];   // [k][m], padded (stride 68 keeps 16B align)
    __shared__ float Ws[16][64];

    const int tid = threadIdx.x;
    const int tx = tid & 15;       // -> m
    const int ty = tid >> 4;       // -> n
    const int m0 = blockIdx.x * 64;
    const int n0 = blockIdx.y * 64;
    const float* Ab = A + (long)blockIdx.z * aBatch;

    const int am = tid >> 2;           // 0..63
    const int ak = (tid & 3) * 4;      // 0..12
    const int wk = tid >> 4;
    const int wn = (tid & 15) * 4;

    float acc[4][4] = {};

    for (int k0 = 0; k0 < 128; k0 += 16) {
        float4 av = *(const float4*)&Ab[(long)(m0 + am) * 128 + k0 + ak];
        float4 wv = *(const float4*)&W[(long)(k0 + wk) * 128 + n0 + wn];
        __syncthreads();
        As[ak + 0][am] = av.x;
        As[ak + 1][am] = av.y;
        As[ak + 2][am] = av.z;
        As[ak + 3][am] = av.w;
        *(float4*)&Ws[wk][wn] = wv;
        __syncthreads();
#pragma unroll
        for (int kk = 0; kk < 16; kk++) {
            float4 a4 = *(const float4*)&As[kk][tx * 4];
            float4 w4 = *(const float4*)&Ws[kk][ty * 4];
            float a[4] = {a4.x, a4.y, a4.z, a4.w};
            float w[4] = {w4.x, w4.y, w4.z, w4.w};
#pragma unroll
            for (int i = 0; i < 4; i++)
#pragma unroll
                for (int j = 0; j < 4; j++)
                    acc[i][j] += a[i] * w[j];
        }
    }
#pragma unroll
    for (int j = 0; j < 4; j++) {
        const int n = n0 + ty * 4 + j;
        const float bv = bias[n];
        float4 r = make_float4(acc[0][j] + bv, acc[1][j] + bv,
                               acc[2][j] + bv, acc[3][j] + bv);
        *(float4*)&out[((long)blockIdx.z * 256 + coff + n) * 4096 + m0 + tx * 4] = r;
    }
}

// ---------------------------------------------------------------------------
extern "C" void kernel_launch(void* const* d_in, const int* in_sizes, int n_in,
                              void* d_out, int out_size)
{
    const float* x        = (const float*)d_in[0];
    const float* l_q_w    = (const float*)d_in[1];
    const float* l_kv_w   = (const float*)d_in[2];
    const float* l_proj_w = (const float*)d_in[3];
    const float* l_proj_b = (const float*)d_in[4];
    const float* h_qkv_w  = (const float*)d_in[5];
    const float* h_proj_w = (const float*)d_in[6];
    const float* h_proj_b = (const float*)d_in[7];
    float* out = (float*)d_out;

    float *qkv, *ql, *pool, *kvl, *oh, *ol;
    cudaGetSymbolAddress((void**)&qkv,  g_qkv);
    cudaGetSymbolAddress((void**)&ql,   g_ql);
    cudaGetSymbolAddress((void**)&pool, g_pool);
    cudaGetSymbolAddress((void**)&kvl,  g_kvl);
    cudaGetSymbolAddress((void**)&oh,   g_oh);
    cudaGetSymbolAddress((void**)&ol,   g_ol);

    // hifi qkv: x^T @ h_qkv_w -> [b][4096][384]
    gemm_xt<<<dim3(64, 6, 8), 256>>>(x, (long)CDIM * NTOK, h_qkv_w,
                                     qkv, (long)NTOK * 384, NTOK, 384);
    // lofi q: x^T @ l_q_w -> [b][4096][128]
    gemm_xt<<<dim3(64, 2, 8), 256>>>(x, (long)CDIM * NTOK, l_q_w,
                                     ql, (long)NTOK * 128, NTOK, 128);
    // 2x2 avg pool -> [b][c][1024]
    pool_kernel<<<BB * CDIM, 256>>>(x);
    // lofi kv: pooled^T @ l_kv_w -> [b][1024][256]
    gemm_xt<<<dim3(16, 4, 8), 256>>>(pool, (long)CDIM * MPOOL, l_kv_w,
                                     kvl, (long)MPOOL * 256, MPOOL, 256);
    // hifi window attention
    hifi_attn<<<4096, 256>>>();
    // lofi global attention
    lofi_attn<<<dim3(16, 32), 256>>>();
    // projections, fused concat+transpose into output
    gemm_proj<<<dim3(64, 2, 8), 256>>>(oh, (long)NTOK * 128, h_proj_w, h_proj_b,
                                       out, 0);
    gemm_proj<<<dim3(64, 2, 8), 256>>>(ol, (long)NTOK * 128, l_proj_w, l_proj_b,
                                       out, 128);
}

// round 4
// speedup vs baseline: 1.0254x; 1.0254x over previous
#include <cuda_runtime.h>

// ---------------------------------------------------------------------------
// HiLo attention, b=8, dim=256, H=W=64, WS=2, 4+4 heads, head_dim=32
// Round 3 resubmit: fp32 + packed f32x2 FMA (FFMA2) in all hot loops.
// (R3 attempt never ran: broker container failure.)
// ---------------------------------------------------------------------------

#define BB 8
#define CDIM 256
#define NTOK 4096          // 64*64 tokens per batch
#define MPOOL 1024         // 32*32 pooled tokens per batch
#define ATTN_SCALE 0.17677669529663687f   // 32^-0.5

typedef unsigned long long u64;

// scratch (device globals; ~117 MB total)
__device__ float g_qkv [BB * NTOK * 384];   // hifi qkv  [b][t][s*128+head*32+d]
__device__ float g_ql  [BB * NTOK * 128];   // lofi q    [b][t][head*32+d]
__device__ float g_pool[BB * CDIM * MPOOL]; // pooled    [b][c][m]  (K-major)
__device__ float g_kvl [BB * MPOOL * 256];  // lofi kv   [b][m][s*128+head*32+d]
__device__ float g_oh  [BB * NTOK * 128];   // hifi attn out
__device__ float g_ol  [BB * NTOK * 128];   // lofi attn out

// ---- packed f32x2 helpers (sm_100a) ---------------------------------------
__device__ __forceinline__ u64 pk2(float lo, float hi) {
    u64 r; asm("mov.b64 %0, {%1, %2};" : "=l"(r) : "f"(lo), "f"(hi)); return r;
}
__device__ __forceinline__ void upk2(u64 v, float& lo, float& hi) {
    asm("mov.b64 {%0, %1}, %2;" : "=f"(lo), "=f"(hi) : "l"(v));
}
__device__ __forceinline__ u64 ffma2(u64 a, u64 b, u64 c) {
    u64 d; asm("fma.rn.f32x2 %0, %1, %2, %3;" : "=l"(d) : "l"(a), "l"(b), "l"(c));
    return d;
}
__device__ __forceinline__ u64 fmul2(u64 a, u64 b) {
    u64 d; asm("mul.rn.f32x2 %0, %1, %2;" : "=l"(d) : "l"(a), "l"(b));
    return d;
}

// ---------------------------------------------------------------------------
// GEMM with A transposed in memory: C[b][m][n] = sum_k A[b][k][m]*W[k][n]
// K = 256. BM=BN=64, BK=16, 256 threads, 4m x 4n per thread (n packed pairs).
// ---------------------------------------------------------------------------
__global__ __launch_bounds__(256) void gemm_xt(
    const float* __restrict__ A, long aBatch,
    const float* __restrict__ W,
    float* __restrict__ Cout, long cBatch,
    int M, int N)
{
    __shared__ float As[16][64];
    __shared__ float Ws[16][64];

    const int tid = threadIdx.x;
    const int tx = tid & 15;       // -> n
    const int ty = tid >> 4;       // -> m
    const int m0 = blockIdx.x * 64;
    const int n0 = blockIdx.y * 64;
    const float* Ab = A + (long)blockIdx.z * aBatch;
    float* Cb = Cout + (long)blockIdx.z * cBatch;

    const int lk = tid >> 4;           // 0..15 (k within tile)
    const int lm = (tid & 15) * 4;     // 0..60

    u64 acc2[4][2];
#pragma unroll
    for (int i = 0; i < 4; i++) { acc2[i][0] = 0ULL; acc2[i][1] = 0ULL; }

    for (int k0 = 0; k0 < 256; k0 += 16) {
        float4 av = *(const float4*)&Ab[(long)(k0 + lk) * M + m0 + lm];
        float4 wv = *(const float4*)&W[(long)(k0 + lk) * N + n0 + lm];
        __syncthreads();
        *(float4*)&As[lk][lm] = av;
        *(float4*)&Ws[lk][lm] = wv;
        __syncthreads();
#pragma unroll
        for (int kk = 0; kk < 16; kk++) {
            float4 a4 = *(const float4*)&As[kk][ty * 4];
            ulonglong2 w2 = *(const ulonglong2*)&Ws[kk][tx * 4];
            u64 a0 = pk2(a4.x, a4.x), a1 = pk2(a4.y, a4.y);
            u64 a2 = pk2(a4.z, a4.z), a3 = pk2(a4.w, a4.w);
            acc2[0][0] = ffma2(a0, w2.x, acc2[0][0]);
            acc2[0][1] = ffma2(a0, w2.y, acc2[0][1]);
            acc2[1][0] = ffma2(a1, w2.x, acc2[1][0]);
            acc2[1][1] = ffma2(a1, w2.y, acc2[1][1]);
            acc2[2][0] = ffma2(a2, w2.x, acc2[2][0]);
            acc2[2][1] = ffma2(a2, w2.y, acc2[2][1]);
            acc2[3][0] = ffma2(a3, w2.x, acc2[3][0]);
            acc2[3][1] = ffma2(a3, w2.y, acc2[3][1]);
        }
    }
#pragma unroll
    for (int i = 0; i < 4; i++) {
        float4 r;
        upk2(acc2[i][0], r.x, r.y);
        upk2(acc2[i][1], r.z, r.w);
        *(float4*)&Cb[(long)(m0 + ty * 4 + i) * N + n0 + tx * 4] = r;
    }
}

// ---------------------------------------------------------------------------
// 2x2 average pool, reading x [b][c][64][64] -> g_pool [b][c][1024]
// ---------------------------------------------------------------------------
__global__ __launch_bounds__(256) void pool_kernel(const float* __restrict__ x)
{
    const int bc = blockIdx.x;                 // b*256 + c
    const float* xp = x + (long)bc * 4096;
    float* pp = g_pool + (long)bc * 1024;
    for (int m = threadIdx.x; m < 1024; m += 256) {
        const int hg = m >> 5, wg = m & 31;
        const float* r0 = xp + (hg * 2) * 64 + wg * 2;
        pp[m] = 0.25f * (r0[0] + r0[1] + r0[64] + r0[65]);
    }
}

// ---------------------------------------------------------------------------
// hifi window attention: one warp per (b, window, head). lane = head dim.
// ---------------------------------------------------------------------------
__global__ __launch_bounds__(256) void hifi_attn()
{
    const int wid = (blockIdx.x * blockDim.x + threadIdx.x) >> 5;
    const int lane = threadIdx.x & 31;
    const int head = wid & 3;
    const int win = (wid >> 2) & 1023;
    const int b = wid >> 12;
    const int hg = win >> 5, wgc = win & 31;

    float q[4], k[4], v[4];
    int t[4];
#pragma unroll
    for (int i = 0; i < 4; i++) {
        const int r = 2 * hg + (i >> 1);
        const int c = 2 * wgc + (i & 1);
        t[i] = r * 64 + c;
        const float* base = g_qkv + (long)(b * NTOK + t[i]) * 384 + head * 32 + lane;
        q[i] = base[0];
        k[i] = base[128];
        v[i] = base[256];
    }
    float s[4][4];
#pragma unroll
    for (int i = 0; i < 4; i++)
#pragma unroll
        for (int j = 0; j < 4; j++) {
            float p = q[i] * k[j];
#pragma unroll
            for (int off = 16; off; off >>= 1)
                p += __shfl_xor_sync(0xffffffffu, p, off);
            s[i][j] = p * ATTN_SCALE;
        }
#pragma unroll
    for (int i = 0; i < 4; i++) {
        float mx = fmaxf(fmaxf(s[i][0], s[i][1]), fmaxf(s[i][2], s[i][3]));
        float e0 = __expf(s[i][0] - mx);
        float e1 = __expf(s[i][1] - mx);
        float e2 = __expf(s[i][2] - mx);
        float e3 = __expf(s[i][3] - mx);
        float inv = 1.0f / (e0 + e1 + e2 + e3);
        float o = (e0 * v[0] + e1 * v[1] + e2 * v[2] + e3 * v[3]) * inv;
        g_oh[(long)(b * NTOK + t[i]) * 128 + head * 32 + lane] = o;
    }
}

// ---------------------------------------------------------------------------
// lofi attention (flash-style, f32x2): 8 warps/block, warp owns 32 q-rows
// (lane = row). KV streamed in 32-row chunks through SMEM; all hot-loop LDS
// are warp-broadcast LDS.128; math is packed FFMA2 along head-dim.
// ---------------------------------------------------------------------------
__global__ __launch_bounds__(256, 2) void lofi_attn()
{
    __shared__ float ks[32][32];
    __shared__ float vs[32][32];

    const int tid = threadIdx.x;
    const int lane = tid & 31;
    const int warp = tid >> 5;
    const int bh = blockIdx.y;            // 0..31
    const int b = bh >> 2, head = bh & 3;
    const int t = blockIdx.x * 256 + warp * 32 + lane;

    const float* qp = g_ql + (long)(b * NTOK + t) * 128 + head * 32;
    u64 q2[16], o2[16];
#pragma unroll
    for (int i = 0; i < 8; i++) {
        ulonglong2 qq = *(const ulonglong2*)&qp[i * 4];
        q2[2 * i] = qq.x; q2[2 * i + 1] = qq.y;
        o2[2 * i] = 0ULL; o2[2 * i + 1] = 0ULL;
    }
    float mrun = -1e30f, lsum = 0.f;

    const float* kvb = g_kvl + (long)b * MPOOL * 256 + head * 32;
    const int lj = tid >> 3;            // 0..31 (kv row in chunk)
    const int ld = (tid & 7) * 4;       // 0..28

    for (int j0 = 0; j0 < MPOOL; j0 += 32) {
        __syncthreads();
        {
            const float* row = kvb + (long)(j0 + lj) * 256;
            *(float4*)&ks[lj][ld] = *(const float4*)&row[ld];
            *(float4*)&vs[lj][ld] = *(const float4*)&row[128 + ld];
        }
        __syncthreads();

        float s[32];
#pragma unroll
        for (int j = 0; j < 32; j++) {
            u64 acc = 0ULL;
#pragma unroll
            for (int dp = 0; dp < 8; dp++) {
                ulonglong2 kk = *(const ulonglong2*)&ks[j][dp * 4];
                acc = ffma2(q2[2 * dp], kk.x, acc);
                acc = ffma2(q2[2 * dp + 1], kk.y, acc);
            }
            float lo, hi; upk2(acc, lo, hi);
            s[j] = (lo + hi) * ATTN_SCALE;
        }
        float cmax = s[0];
#pragma unroll
        for (int j = 1; j < 32; j++) cmax = fmaxf(cmax, s[j]);
        const float mnew = fmaxf(mrun, cmax);
        const float sf = __expf(mrun - mnew);
        mrun = mnew;
        lsum *= sf;
        const u64 sf2 = pk2(sf, sf);
#pragma unroll
        for (int dp = 0; dp < 16; dp++) o2[dp] = fmul2(o2[dp], sf2);
#pragma unroll
        for (int j = 0; j < 32; j++) { s[j] = __expf(s[j] - mnew); lsum += s[j]; }
#pragma unroll
        for (int j = 0; j < 32; j++) {
            const u64 sj2 = pk2(s[j], s[j]);
#pragma unroll
            for (int dp = 0; dp < 8; dp++) {
                ulonglong2 vv = *(const ulonglong2*)&vs[j][dp * 4];
                o2[2 * dp]     = ffma2(sj2, vv.x, o2[2 * dp]);
                o2[2 * dp + 1] = ffma2(sj2, vv.y, o2[2 * dp + 1]);
            }
        }
    }
    const float inv = 1.0f / lsum;
    const u64 inv2 = pk2(inv, inv);
    float* op = g_ol + (long)(b * NTOK + t) * 128 + head * 32;
#pragma unroll
    for (int i = 0; i < 8; i++) {
        ulonglong2 r;
        r.x = fmul2(o2[2 * i], inv2);
        r.y = fmul2(o2[2 * i + 1], inv2);
        *(ulonglong2*)&op[i * 4] = r;
    }
}

// ---------------------------------------------------------------------------
// Projection GEMM: out[(b*256+coff+n)*4096+m] = bias[n] + sum_k A[b][m][k]*W[k][n]
// A row-major [M][128]. Fused concat+transpose into the chw output.
// Packed pairs along m.
// ---------------------------------------------------------------------------
__global__ __launch_bounds__(256) void gemm_proj(
    const float* __restrict__ A, long aBatch,
    const float* __restrict__ W,
    const float* __restrict__ bias,
    float* __restrict__ out, int coff)
{
    __shared__ float As[16][68];   // [k][m], stride 68 floats = 272B (16B mult)
    __shared__ float Ws[16][64];

    const int tid = threadIdx.x;
    const int tx = tid & 15;       // -> m
    const int ty = tid >> 4;       // -> n
    const int m0 = blockIdx.x * 64;
    const int n0 = blockIdx.y * 64;
    const float* Ab = A + (long)blockIdx.z * aBatch;

    const int am = tid >> 2;           // 0..63
    const int ak = (tid & 3) * 4;      // 0..12
    const int wk = tid >> 4;
    const int wn = (tid & 15) * 4;

    u64 acc2[2][4];
#pragma unroll
    for (int j = 0; j < 4; j++) { acc2[0][j] = 0ULL; acc2[1][j] = 0ULL; }

    for (int k0 = 0; k0 < 128; k0 += 16) {
        float4 av = *(const float4*)&Ab[(long)(m0 + am) * 128 + k0 + ak];
        float4 wv = *(const float4*)&W[(long)(k0 + wk) * 128 + n0 + wn];
        __syncthreads();
        As[ak + 0][am] = av.x;
        As[ak + 1][am] = av.y;
        As[ak + 2][am] = av.z;
        As[ak + 3][am] = av.w;
        *(float4*)&Ws[wk][wn] = wv;
        __syncthreads();
#pragma unroll
        for (int kk = 0; kk < 16; kk++) {
            ulonglong2 a2 = *(const ulonglong2*)&As[kk][tx * 4];
            float4 w4 = *(const float4*)&Ws[kk][ty * 4];
            u64 w0 = pk2(w4.x, w4.x), w1 = pk2(w4.y, w4.y);
            u64 w2 = pk2(w4.z, w4.z), w3 = pk2(w4.w, w4.w);
            acc2[0][0] = ffma2(a2.x, w0, acc2[0][0]);
            acc2[1][0] = ffma2(a2.y, w0, acc2[1][0]);
            acc2[0][1] = ffma2(a2.x, w1, acc2[0][1]);
            acc2[1][1] = ffma2(a2.y, w1, acc2[1][1]);
            acc2[0][2] = ffma2(a2.x, w2, acc2[0][2]);
            acc2[1][2] = ffma2(a2.y, w2, acc2[1][2]);
            acc2[0][3] = ffma2(a2.x, w3, acc2[0][3]);
            acc2[1][3] = ffma2(a2.y, w3, acc2[1][3]);
        }
    }
#pragma unroll
    for (int j = 0; j < 4; j++) {
        const int n = n0 + ty * 4 + j;
        const float bv = bias[n];
        float4 r;
        upk2(acc2[0][j], r.x, r.y);
        upk2(acc2[1][j], r.z, r.w);
        r.x += bv; r.y += bv; r.z += bv; r.w += bv;
        *(float4*)&out[((long)blockIdx.z * 256 + coff + n) * 4096 + m0 + tx * 4] = r;
    }
}

// ---------------------------------------------------------------------------
extern "C" void kernel_launch(void* const* d_in, const int* in_sizes, int n_in,
                              void* d_out, int out_size)
{
    const float* x        = (const float*)d_in[0];
    const float* l_q_w    = (const float*)d_in[1];
    const float* l_kv_w   = (const float*)d_in[2];
    const float* l_proj_w = (const float*)d_in[3];
    const float* l_proj_b = (const float*)d_in[4];
    const float* h_qkv_w  = (const float*)d_in[5];
    const float* h_proj_w = (const float*)d_in[6];
    const float* h_proj_b = (const float*)d_in[7];
    float* out = (float*)d_out;

    float *qkv, *ql, *pool, *kvl, *oh, *ol;
    cudaGetSymbolAddress((void**)&qkv,  g_qkv);
    cudaGetSymbolAddress((void**)&ql,   g_ql);
    cudaGetSymbolAddress((void**)&pool, g_pool);
    cudaGetSymbolAddress((void**)&kvl,  g_kvl);
    cudaGetSymbolAddress((void**)&oh,   g_oh);
    cudaGetSymbolAddress((void**)&ol,   g_ol);

    // hifi qkv: x^T @ h_qkv_w -> [b][4096][384]
    gemm_xt<<<dim3(64, 6, 8), 256>>>(x, (long)CDIM * NTOK, h_qkv_w,
                                     qkv, (long)NTOK * 384, NTOK, 384);
    // lofi q: x^T @ l_q_w -> [b][4096][128]
    gemm_xt<<<dim3(64, 2, 8), 256>>>(x, (long)CDIM * NTOK, l_q_w,
                                     ql, (long)NTOK * 128, NTOK, 128);
    // 2x2 avg pool -> [b][c][1024]
    pool_kernel<<<BB * CDIM, 256>>>(x);
    // lofi kv: pooled^T @ l_kv_w -> [b][1024][256]
    gemm_xt<<<dim3(16, 4, 8), 256>>>(pool, (long)CDIM * MPOOL, l_kv_w,
                                     kvl, (long)MPOOL * 256, MPOOL, 256);
    // hifi window attention
    hifi_attn<<<4096, 256>>>();
    // lofi global attention
    lofi_attn<<<dim3(16, 32), 256>>>();
    // projections, fused concat+transpose into output
    gemm_proj<<<dim3(64, 2, 8), 256>>>(oh, (long)NTOK * 128, h_proj_w, h_proj_b,
                                       out, 0);
    gemm_proj<<<dim3(64, 2, 8), 256>>>(ol, (long)NTOK * 128, l_proj_w, l_proj_b,
                                       out, 128);
}

// round 5
// speedup vs baseline: 1.0978x; 1.0706x over previous
#include <cuda_runtime.h>

// ---------------------------------------------------------------------------
// HiLo attention, b=8, dim=256, H=W=64, WS=2, 4+4 heads, head_dim=32
// Round 5: GEMMs moved to tensor pipe (mma.sync m16n8k8 tf32, 3xTF32 split).
// Attention kernels unchanged (FFMA2 flash lofi + warp hifi).
// ---------------------------------------------------------------------------

#define BB 8
#define CDIM 256
#define NTOK 4096          // 64*64 tokens per batch
#define MPOOL 1024         // 32*32 pooled tokens per batch
#define ATTN_SCALE 0.17677669529663687f   // 32^-0.5

typedef unsigned long long u64;
typedef unsigned int u32;

// scratch (device globals; ~117 MB total)
__device__ float g_qkv [BB * NTOK * 384];   // hifi qkv  [b][t][s*128+head*32+d]
__device__ float g_ql  [BB * NTOK * 128];   // lofi q    [b][t][head*32+d]
__device__ float g_pool[BB * CDIM * MPOOL]; // pooled    [b][c][m]  (K-major)
__device__ float g_kvl [BB * MPOOL * 256];  // lofi kv   [b][m][s*128+head*32+d]
__device__ float g_oh  [BB * NTOK * 128];   // hifi attn out
__device__ float g_ol  [BB * NTOK * 128];   // lofi attn out

// ---- packed f32x2 helpers (sm_100a) ---------------------------------------
__device__ __forceinline__ u64 pk2(float lo, float hi) {
    u64 r; asm("mov.b64 %0, {%1, %2};" : "=l"(r) : "f"(lo), "f"(hi)); return r;
}
__device__ __forceinline__ void upk2(u64 v, float& lo, float& hi) {
    asm("mov.b64 {%0, %1}, %2;" : "=f"(lo), "=f"(hi) : "l"(v));
}
__device__ __forceinline__ u64 ffma2(u64 a, u64 b, u64 c) {
    u64 d; asm("fma.rn.f32x2 %0, %1, %2, %3;" : "=l"(d) : "l"(a), "l"(b), "l"(c));
    return d;
}
__device__ __forceinline__ u64 fmul2(u64 a, u64 b) {
    u64 d; asm("mul.rn.f32x2 %0, %1, %2;" : "=l"(d) : "l"(a), "l"(b));
    return d;
}

// ---- tf32 mma helpers ------------------------------------------------------
__device__ __forceinline__ u32 tf32_hi(float x) {
    u32 r; asm("cvt.rna.tf32.f32 %0, %1;" : "=r"(r) : "f"(x)); return r;
}
// residual (second-order term; raw f32 bits are fine, HW truncates)
__device__ __forceinline__ u32 tf32_lo(float x, u32 hi) {
    return __float_as_uint(x - __uint_as_float(hi));
}
__device__ __forceinline__ void mma_tf32(
    float& c0, float& c1, float& c2, float& c3,
    u32 a0, u32 a1, u32 a2, u32 a3, u32 b0, u32 b1)
{
    asm volatile(
        "mma.sync.aligned.m16n8k8.row.col.f32.tf32.tf32.f32 "
        "{%0,%1,%2,%3}, {%4,%5,%6,%7}, {%8,%9}, {%0,%1,%2,%3};\n"
        : "+f"(c0), "+f"(c1), "+f"(c2), "+f"(c3)
        : "r"(a0), "r"(a1), "r"(a2), "r"(a3), "r"(b0), "r"(b1));
}

// ---------------------------------------------------------------------------
// Tensor-core GEMM, A K-major: C[b][m][n] = sum_k A[b][k][m] * W[k][n], K=256.
// BM=128, BN=64, BK=32, 256 thr (8 warps: 4 m x 2 n). 3xTF32 split.
// ---------------------------------------------------------------------------
__global__ __launch_bounds__(256) void gemm_xt_mma(
    const float* __restrict__ A, long aBatch,
    const float* __restrict__ W,
    float* __restrict__ Cout, long cBatch,
    int M, int N)
{
    __shared__ float As[32][132];   // [k][m]
    __shared__ float Ws[32][68];    // [k][n]

    const int tid = threadIdx.x;
    const int wid = tid >> 5;
    const int lane = tid & 31;
    const int g = lane >> 2;        // group 0..7
    const int tg = lane & 3;        // thread-in-group 0..3
    const int m0 = blockIdx.x * 128;
    const int n0 = blockIdx.y * 64;
    const int wm = (wid & 3) * 32;  // warp m offset in tile
    const int wn = (wid >> 2) * 32; // warp n offset in tile
    const float* Ab = A + (long)blockIdx.z * aBatch;
    float* Cb = Cout + (long)blockIdx.z * cBatch;

    float acc[2][4][4];             // [mi][nj][c0..3]
#pragma unroll
    for (int i = 0; i < 2; i++)
#pragma unroll
        for (int j = 0; j < 4; j++)
#pragma unroll
            for (int c = 0; c < 4; c++) acc[i][j][c] = 0.f;

    for (int k0 = 0; k0 < 256; k0 += 32) {
        // stage gmem -> regs
        float4 av[4], wv[2];
#pragma unroll
        for (int p = 0; p < 4; p++) {
            const int idx = tid + 256 * p;
            av[p] = *(const float4*)&Ab[(long)(k0 + (idx >> 5)) * M + m0 + (idx & 31) * 4];
        }
#pragma unroll
        for (int p = 0; p < 2; p++) {
            const int idx = tid + 256 * p;
            wv[p] = *(const float4*)&W[(long)(k0 + (idx >> 4)) * N + n0 + (idx & 15) * 4];
        }
        __syncthreads();
#pragma unroll
        for (int p = 0; p < 4; p++) {
            const int idx = tid + 256 * p;
            *(float4*)&As[idx >> 5][(idx & 31) * 4] = av[p];
        }
#pragma unroll
        for (int p = 0; p < 2; p++) {
            const int idx = tid + 256 * p;
            *(float4*)&Ws[idx >> 4][(idx & 15) * 4] = wv[p];
        }
        __syncthreads();

#pragma unroll
        for (int ks = 0; ks < 4; ks++) {
            const int kk = ks * 8;
            // A fragments (2 m-tiles of 16)
            u32 ah[2][4], al[2][4];
#pragma unroll
            for (int i = 0; i < 2; i++) {
                const int mb = wm + i * 16;
                float f0 = As[kk + tg][mb + g];
                float f1 = As[kk + tg][mb + g + 8];
                float f2 = As[kk + tg + 4][mb + g];
                float f3 = As[kk + tg + 4][mb + g + 8];
                ah[i][0] = tf32_hi(f0); al[i][0] = tf32_lo(f0, ah[i][0]);
                ah[i][1] = tf32_hi(f1); al[i][1] = tf32_lo(f1, ah[i][1]);
                ah[i][2] = tf32_hi(f2); al[i][2] = tf32_lo(f2, ah[i][2]);
                ah[i][3] = tf32_hi(f3); al[i][3] = tf32_lo(f3, ah[i][3]);
            }
            // B fragments (4 n-tiles of 8)
            u32 bh[4][2], bl[4][2];
#pragma unroll
            for (int j = 0; j < 4; j++) {
                const int nb = wn + j * 8;
                float f0 = Ws[kk + tg][nb + g];
                float f1 = Ws[kk + tg + 4][nb + g];
                bh[j][0] = tf32_hi(f0); bl[j][0] = tf32_lo(f0, bh[j][0]);
                bh[j][1] = tf32_hi(f1); bl[j][1] = tf32_lo(f1, bh[j][1]);
            }
#pragma unroll
            for (int i = 0; i < 2; i++)
#pragma unroll
                for (int j = 0; j < 4; j++) {
                    float* c = acc[i][j];
                    mma_tf32(c[0], c[1], c[2], c[3],
                             ah[i][0], ah[i][1], ah[i][2], ah[i][3],
                             bh[j][0], bh[j][1]);
                    mma_tf32(c[0], c[1], c[2], c[3],
                             al[i][0], al[i][1], al[i][2], al[i][3],
                             bh[j][0], bh[j][1]);
                    mma_tf32(c[0], c[1], c[2], c[3],
                             ah[i][0], ah[i][1], ah[i][2], ah[i][3],
                             bl[j][0], bl[j][1]);
                }
        }
    }

    // epilogue: D[m][n], row = g (+8), cols = 2*tg, 2*tg+1
#pragma unroll
    for (int i = 0; i < 2; i++)
#pragma unroll
        for (int j = 0; j < 4; j++) {
            const int row = m0 + wm + i * 16 + g;
            const int col = n0 + wn + j * 8 + 2 * tg;
            float2 r0 = make_float2(acc[i][j][0], acc[i][j][1]);
            float2 r1 = make_float2(acc[i][j][2], acc[i][j][3]);
            *(float2*)&Cb[(long)row * N + col] = r0;
            *(float2*)&Cb[(long)(row + 8) * N + col] = r1;
        }
}

// ---------------------------------------------------------------------------
// Tensor-core projection GEMM, K=128:
// out[(b*256+coff+n)*4096 + m] = bias[n] + sum_k A[b][m][k] * W[k][n]
// A row-major [M][128]. BM=128, BN=64, BK=32. Fused concat+transpose store.
// ---------------------------------------------------------------------------
__global__ __launch_bounds__(256) void gemm_proj_mma(
    const float* __restrict__ A, long aBatch,
    const float* __restrict__ W,
    const float* __restrict__ bias,
    float* __restrict__ out, int coff)
{
    __shared__ float As[128][36];   // [m][k]
    __shared__ float Ws[32][68];    // [k][n]

    const int tid = threadIdx.x;
    const int wid = tid >> 5;
    const int lane = tid & 31;
    const int g = lane >> 2;
    const int tg = lane & 3;
    const int m0 = blockIdx.x * 128;
    const int n0 = blockIdx.y * 64;
    const int wm = (wid & 3) * 32;
    const int wn = (wid >> 2) * 32;
    const float* Ab = A + (long)blockIdx.z * aBatch;

    float acc[2][4][4];
#pragma unroll
    for (int i = 0; i < 2; i++)
#pragma unroll
        for (int j = 0; j < 4; j++)
#pragma unroll
            for (int c = 0; c < 4; c++) acc[i][j][c] = 0.f;

    for (int k0 = 0; k0 < 128; k0 += 32) {
        float4 av[4], wv[2];
#pragma unroll
        for (int p = 0; p < 4; p++) {
            const int idx = tid + 256 * p;
            av[p] = *(const float4*)&Ab[(long)(m0 + (idx >> 3)) * 128 + k0 + (idx & 7) * 4];
        }
#pragma unroll
        for (int p = 0; p < 2; p++) {
            const int idx = tid + 256 * p;
            wv[p] = *(const float4*)&W[(long)(k0 + (idx >> 4)) * 128 + n0 + (idx & 15) * 4];
        }
        __syncthreads();
#pragma unroll
        for (int p = 0; p < 4; p++) {
            const int idx = tid + 256 * p;
            *(float4*)&As[idx >> 3][(idx & 7) * 4] = av[p];
        }
#pragma unroll
        for (int p = 0; p < 2; p++) {
            const int idx = tid + 256 * p;
            *(float4*)&Ws[idx >> 4][(idx & 15) * 4] = wv[p];
        }
        __syncthreads();

#pragma unroll
        for (int ks = 0; ks < 4; ks++) {
            const int kk = ks * 8;
            u32 ah[2][4], al[2][4];
#pragma unroll
            for (int i = 0; i < 2; i++) {
                const int mb = wm + i * 16;
                float f0 = As[mb + g][kk + tg];
                float f1 = As[mb + g + 8][kk + tg];
                float f2 = As[mb + g][kk + tg + 4];
                float f3 = As[mb + g + 8][kk + tg + 4];
                ah[i][0] = tf32_hi(f0); al[i][0] = tf32_lo(f0, ah[i][0]);
                ah[i][1] = tf32_hi(f1); al[i][1] = tf32_lo(f1, ah[i][1]);
                ah[i][2] = tf32_hi(f2); al[i][2] = tf32_lo(f2, ah[i][2]);
                ah[i][3] = tf32_hi(f3); al[i][3] = tf32_lo(f3, ah[i][3]);
            }
            u32 bh[4][2], bl[4][2];
#pragma unroll
            for (int j = 0; j < 4; j++) {
                const int nb = wn + j * 8;
                float f0 = Ws[kk + tg][nb + g];
                float f1 = Ws[kk + tg + 4][nb + g];
                bh[j][0] = tf32_hi(f0); bl[j][0] = tf32_lo(f0, bh[j][0]);
                bh[j][1] = tf32_hi(f1); bl[j][1] = tf32_lo(f1, bh[j][1]);
            }
#pragma unroll
            for (int i = 0; i < 2; i++)
#pragma unroll
                for (int j = 0; j < 4; j++) {
                    float* c = acc[i][j];
                    mma_tf32(c[0], c[1], c[2], c[3],
                             ah[i][0], ah[i][1], ah[i][2], ah[i][3],
                             bh[j][0], bh[j][1]);
                    mma_tf32(c[0], c[1], c[2], c[3],
                             al[i][0], al[i][1], al[i][2], al[i][3],
                             bh[j][0], bh[j][1]);
                    mma_tf32(c[0], c[1], c[2], c[3],
                             ah[i][0], ah[i][1], ah[i][2], ah[i][3],
                             bl[j][0], bl[j][1]);
                }
        }
    }

    // epilogue: transposed store out[(b*256+coff+n)*4096 + m] + bias
    float* ob = out + ((long)blockIdx.z * 256 + coff) * 4096;
#pragma unroll
    for (int j = 0; j < 4; j++) {
        const int nl = n0 + wn + j * 8 + 2 * tg;
        const float bv0 = bias[nl];
        const float bv1 = bias[nl + 1];
#pragma unroll
        for (int i = 0; i < 2; i++) {
            const int m = m0 + wm + i * 16 + g;
            ob[(long)nl * 4096 + m]           = acc[i][j][0] + bv0;
            ob[(long)(nl + 1) * 4096 + m]     = acc[i][j][1] + bv1;
            ob[(long)nl * 4096 + m + 8]       = acc[i][j][2] + bv0;
            ob[(long)(nl + 1) * 4096 + m + 8] = acc[i][j][3] + bv1;
        }
    }
}

// ---------------------------------------------------------------------------
// 2x2 average pool, reading x [b][c][64][64] -> g_pool [b][c][1024]
// ---------------------------------------------------------------------------
__global__ __launch_bounds__(256) void pool_kernel(const float* __restrict__ x)
{
    const int bc = blockIdx.x;                 // b*256 + c
    const float* xp = x + (long)bc * 4096;
    float* pp = g_pool + (long)bc * 1024;
    for (int m = threadIdx.x; m < 1024; m += 256) {
        const int hg = m >> 5, wg = m & 31;
        const float* r0 = xp + (hg * 2) * 64 + wg * 2;
        pp[m] = 0.25f * (r0[0] + r0[1] + r0[64] + r0[65]);
    }
}

// ---------------------------------------------------------------------------
// hifi window attention: one warp per (b, window, head). lane = head dim.
// ---------------------------------------------------------------------------
__global__ __launch_bounds__(256) void hifi_attn()
{
    const int wid = (blockIdx.x * blockDim.x + threadIdx.x) >> 5;
    const int lane = threadIdx.x & 31;
    const int head = wid & 3;
    const int win = (wid >> 2) & 1023;
    const int b = wid >> 12;
    const int hg = win >> 5, wgc = win & 31;

    float q[4], k[4], v[4];
    int t[4];
#pragma unroll
    for (int i = 0; i < 4; i++) {
        const int r = 2 * hg + (i >> 1);
        const int c = 2 * wgc + (i & 1);
        t[i] = r * 64 + c;
        const float* base = g_qkv + (long)(b * NTOK + t[i]) * 384 + head * 32 + lane;
        q[i] = base[0];
        k[i] = base[128];
        v[i] = base[256];
    }
    float s[4][4];
#pragma unroll
    for (int i = 0; i < 4; i++)
#pragma unroll
        for (int j = 0; j < 4; j++) {
            float p = q[i] * k[j];
#pragma unroll
            for (int off = 16; off; off >>= 1)
                p += __shfl_xor_sync(0xffffffffu, p, off);
            s[i][j] = p * ATTN_SCALE;
        }
#pragma unroll
    for (int i = 0; i < 4; i++) {
        float mx = fmaxf(fmaxf(s[i][0], s[i][1]), fmaxf(s[i][2], s[i][3]));
        float e0 = __expf(s[i][0] - mx);
        float e1 = __expf(s[i][1] - mx);
        float e2 = __expf(s[i][2] - mx);
        float e3 = __expf(s[i][3] - mx);
        float inv = 1.0f / (e0 + e1 + e2 + e3);
        float o = (e0 * v[0] + e1 * v[1] + e2 * v[2] + e3 * v[3]) * inv;
        g_oh[(long)(b * NTOK + t[i]) * 128 + head * 32 + lane] = o;
    }
}

// ---------------------------------------------------------------------------
// lofi attention (flash-style, f32x2): 8 warps/block, warp owns 32 q-rows
// (lane = row). KV streamed in 32-row chunks through SMEM; hot-loop LDS are
// warp-broadcast LDS.128; math is packed FFMA2 along head-dim.
// ---------------------------------------------------------------------------
__global__ __launch_bounds__(256, 2) void lofi_attn()
{
    __shared__ float ks[32][32];
    __shared__ float vs[32][32];

    const int tid = threadIdx.x;
    const int lane = tid & 31;
    const int warp = tid >> 5;
    const int bh = blockIdx.y;            // 0..31
    const int b = bh >> 2, head = bh & 3;
    const int t = blockIdx.x * 256 + warp * 32 + lane;

    const float* qp = g_ql + (long)(b * NTOK + t) * 128 + head * 32;
    u64 q2[16], o2[16];
#pragma unroll
    for (int i = 0; i < 8; i++) {
        ulonglong2 qq = *(const ulonglong2*)&qp[i * 4];
        q2[2 * i] = qq.x; q2[2 * i + 1] = qq.y;
        o2[2 * i] = 0ULL; o2[2 * i + 1] = 0ULL;
    }
    float mrun = -1e30f, lsum = 0.f;

    const float* kvb = g_kvl + (long)b * MPOOL * 256 + head * 32;
    const int lj = tid >> 3;            // 0..31 (kv row in chunk)
    const int ld = (tid & 7) * 4;       // 0..28

    for (int j0 = 0; j0 < MPOOL; j0 += 32) {
        __syncthreads();
        {
            const float* row = kvb + (long)(j0 + lj) * 256;
            *(float4*)&ks[lj][ld] = *(const float4*)&row[ld];
            *(float4*)&vs[lj][ld] = *(const float4*)&row[128 + ld];
        }
        __syncthreads();

        float s[32];
#pragma unroll
        for (int j = 0; j < 32; j++) {
            u64 acc = 0ULL;
#pragma unroll
            for (int dp = 0; dp < 8; dp++) {
                ulonglong2 kk = *(const ulonglong2*)&ks[j][dp * 4];
                acc = ffma2(q2[2 * dp], kk.x, acc);
                acc = ffma2(q2[2 * dp + 1], kk.y, acc);
            }
            float lo, hi; upk2(acc, lo, hi);
            s[j] = (lo + hi) * ATTN_SCALE;
        }
        float cmax = s[0];
#pragma unroll
        for (int j = 1; j < 32; j++) cmax = fmaxf(cmax, s[j]);
        const float mnew = fmaxf(mrun, cmax);
        const float sf = __expf(mrun - mnew);
        mrun = mnew;
        lsum *= sf;
        const u64 sf2 = pk2(sf, sf);
#pragma unroll
        for (int dp = 0; dp < 16; dp++) o2[dp] = fmul2(o2[dp], sf2);
#pragma unroll
        for (int j = 0; j < 32; j++) { s[j] = __expf(s[j] - mnew); lsum += s[j]; }
#pragma unroll
        for (int j = 0; j < 32; j++) {
            const u64 sj2 = pk2(s[j], s[j]);
#pragma unroll
            for (int dp = 0; dp < 8; dp++) {
                ulonglong2 vv = *(const ulonglong2*)&vs[j][dp * 4];
                o2[2 * dp]     = ffma2(sj2, vv.x, o2[2 * dp]);
                o2[2 * dp + 1] = ffma2(sj2, vv.y, o2[2 * dp + 1]);
            }
        }
    }
    const float inv = 1.0f / lsum;
    const u64 inv2 = pk2(inv, inv);
    float* op = g_ol + (long)(b * NTOK + t) * 128 + head * 32;
#pragma unroll
    for (int i = 0; i < 8; i++) {
        ulonglong2 r;
        r.x = fmul2(o2[2 * i], inv2);
        r.y = fmul2(o2[2 * i + 1], inv2);
        *(ulonglong2*)&op[i * 4] = r;
    }
}

// ---------------------------------------------------------------------------
extern "C" void kernel_launch(void* const* d_in, const int* in_sizes, int n_in,
                              void* d_out, int out_size)
{
    const float* x        = (const float*)d_in[0];
    const float* l_q_w    = (const float*)d_in[1];
    const float* l_kv_w   = (const float*)d_in[2];
    const float* l_proj_w = (const float*)d_in[3];
    const float* l_proj_b = (const float*)d_in[4];
    const float* h_qkv_w  = (const float*)d_in[5];
    const float* h_proj_w = (const float*)d_in[6];
    const float* h_proj_b = (const float*)d_in[7];
    float* out = (float*)d_out;

    float *qkv, *ql, *pool, *kvl, *oh, *ol;
    cudaGetSymbolAddress((void**)&qkv,  g_qkv);
    cudaGetSymbolAddress((void**)&ql,   g_ql);
    cudaGetSymbolAddress((void**)&pool, g_pool);
    cudaGetSymbolAddress((void**)&kvl,  g_kvl);
    cudaGetSymbolAddress((void**)&oh,   g_oh);
    cudaGetSymbolAddress((void**)&ol,   g_ol);

    // hifi qkv: x^T @ h_qkv_w -> [b][4096][384]
    gemm_xt_mma<<<dim3(32, 6, 8), 256>>>(x, (long)CDIM * NTOK, h_qkv_w,
                                         qkv, (long)NTOK * 384, NTOK, 384);
    // lofi q: x^T @ l_q_w -> [b][4096][128]
    gemm_xt_mma<<<dim3(32, 2, 8), 256>>>(x, (long)CDIM * NTOK, l_q_w,
                                         ql, (long)NTOK * 128, NTOK, 128);
    // 2x2 avg pool -> [b][c][1024]
    pool_kernel<<<BB * CDIM, 256>>>(x);
    // lofi kv: pooled^T @ l_kv_w -> [b][1024][256]
    gemm_xt_mma<<<dim3(8, 4, 8), 256>>>(pool, (long)CDIM * MPOOL, l_kv_w,
                                        kvl, (long)MPOOL * 256, MPOOL, 256);
    // hifi window attention
    hifi_attn<<<4096, 256>>>();
    // lofi global attention
    lofi_attn<<<dim3(16, 32), 256>>>();
    // projections, fused concat+transpose into output
    gemm_proj_mma<<<dim3(32, 2, 8), 256>>>(oh, (long)NTOK * 128, h_proj_w, h_proj_b,
                                           out, 0);
    gemm_proj_mma<<<dim3(32, 2, 8), 256>>>(ol, (long)NTOK * 128, l_proj_w, l_proj_b,
                                           out, 128);
}

// round 6
// speedup vs baseline: 2.0218x; 1.8417x over previous
#include <cuda_runtime.h>
#include <cuda_bf16.h>

// ---------------------------------------------------------------------------
// HiLo attention, b=8, dim=256, H=W=64, WS=2, 4+4 heads, head_dim=32
// Round 6: lofi attention rewritten as FA2-style tensor-core flash kernel
// (m16n8k16 bf16, 3-pass hi/lo splits for QK^T and PV).
// GEMMs unchanged from R5 (mma tf32x3).
// ---------------------------------------------------------------------------

#define BB 8
#define CDIM 256
#define NTOK 4096          // 64*64 tokens per batch
#define MPOOL 1024         // 32*32 pooled tokens per batch
#define ATTN_SCALE 0.17677669529663687f   // 32^-0.5

typedef unsigned long long u64;
typedef unsigned int u32;

// scratch (device globals; ~117 MB total)
__device__ float g_qkv [BB * NTOK * 384];   // hifi qkv  [b][t][s*128+head*32+d]
__device__ float g_ql  [BB * NTOK * 128];   // lofi q    [b][t][head*32+d]
__device__ float g_pool[BB * CDIM * MPOOL]; // pooled    [b][c][m]  (K-major)
__device__ float g_kvl [BB * MPOOL * 256];  // lofi kv   [b][m][s*128+head*32+d]
__device__ float g_oh  [BB * NTOK * 128];   // hifi attn out
__device__ float g_ol  [BB * NTOK * 128];   // lofi attn out

// ---- tf32 mma helpers (GEMMs) ---------------------------------------------
__device__ __forceinline__ u32 tf32_hi(float x) {
    u32 r; asm("cvt.rna.tf32.f32 %0, %1;" : "=r"(r) : "f"(x)); return r;
}
__device__ __forceinline__ u32 tf32_lo(float x, u32 hi) {
    return __float_as_uint(x - __uint_as_float(hi));
}
__device__ __forceinline__ void mma_tf32(
    float& c0, float& c1, float& c2, float& c3,
    u32 a0, u32 a1, u32 a2, u32 a3, u32 b0, u32 b1)
{
    asm volatile(
        "mma.sync.aligned.m16n8k8.row.col.f32.tf32.tf32.f32 "
        "{%0,%1,%2,%3}, {%4,%5,%6,%7}, {%8,%9}, {%0,%1,%2,%3};\n"
        : "+f"(c0), "+f"(c1), "+f"(c2), "+f"(c3)
        : "r"(a0), "r"(a1), "r"(a2), "r"(a3), "r"(b0), "r"(b1));
}

// ---- bf16 mma helpers (lofi attention) ------------------------------------
__device__ __forceinline__ void mma_bf16(
    float* c, const u32* a, u32 b0, u32 b1)
{
    asm volatile(
        "mma.sync.aligned.m16n8k16.row.col.f32.bf16.bf16.f32 "
        "{%0,%1,%2,%3}, {%4,%5,%6,%7}, {%8,%9}, {%0,%1,%2,%3};\n"
        : "+f"(c[0]), "+f"(c[1]), "+f"(c[2]), "+f"(c[3])
        : "r"(a[0]), "r"(a[1]), "r"(a[2]), "r"(a[3]), "r"(b0), "r"(b1));
}
// split two floats into packed bf16x2 hi + residual bf16x2 lo
// packed layout: low half = x0, high half = x1  (matches f16x2 fragment order)
__device__ __forceinline__ void bf16_split2(float x0, float x1, u32& hi, u32& lo)
{
    asm("cvt.rn.bf16x2.f32 %0, %1, %2;" : "=r"(hi) : "f"(x1), "f"(x0));
    float h0 = __uint_as_float(hi << 16);
    float h1 = __uint_as_float(hi & 0xffff0000u);
    asm("cvt.rn.bf16x2.f32 %0, %1, %2;" : "=r"(lo) : "f"(x1 - h1), "f"(x0 - h0));
}

// ---------------------------------------------------------------------------
// Tensor-core GEMM, A K-major: C[b][m][n] = sum_k A[b][k][m] * W[k][n], K=256.
// BM=128, BN=64, BK=32, 256 thr (8 warps: 4 m x 2 n). 3xTF32 split.
// ---------------------------------------------------------------------------
__global__ __launch_bounds__(256) void gemm_xt_mma(
    const float* __restrict__ A, long aBatch,
    const float* __restrict__ W,
    float* __restrict__ Cout, long cBatch,
    int M, int N)
{
    __shared__ float As[32][132];   // [k][m]
    __shared__ float Ws[32][68];    // [k][n]

    const int tid = threadIdx.x;
    const int wid = tid >> 5;
    const int lane = tid & 31;
    const int g = lane >> 2;
    const int tg = lane & 3;
    const int m0 = blockIdx.x * 128;
    const int n0 = blockIdx.y * 64;
    const int wm = (wid & 3) * 32;
    const int wn = (wid >> 2) * 32;
    const float* Ab = A + (long)blockIdx.z * aBatch;
    float* Cb = Cout + (long)blockIdx.z * cBatch;

    float acc[2][4][4];
#pragma unroll
    for (int i = 0; i < 2; i++)
#pragma unroll
        for (int j = 0; j < 4; j++)
#pragma unroll
            for (int c = 0; c < 4; c++) acc[i][j][c] = 0.f;

    for (int k0 = 0; k0 < 256; k0 += 32) {
        float4 av[4], wv[2];
#pragma unroll
        for (int p = 0; p < 4; p++) {
            const int idx = tid + 256 * p;
            av[p] = *(const float4*)&Ab[(long)(k0 + (idx >> 5)) * M + m0 + (idx & 31) * 4];
        }
#pragma unroll
        for (int p = 0; p < 2; p++) {
            const int idx = tid + 256 * p;
            wv[p] = *(const float4*)&W[(long)(k0 + (idx >> 4)) * N + n0 + (idx & 15) * 4];
        }
        __syncthreads();
#pragma unroll
        for (int p = 0; p < 4; p++) {
            const int idx = tid + 256 * p;
            *(float4*)&As[idx >> 5][(idx & 31) * 4] = av[p];
        }
#pragma unroll
        for (int p = 0; p < 2; p++) {
            const int idx = tid + 256 * p;
            *(float4*)&Ws[idx >> 4][(idx & 15) * 4] = wv[p];
        }
        __syncthreads();

#pragma unroll
        for (int ks = 0; ks < 4; ks++) {
            const int kk = ks * 8;
            u32 ah[2][4], al[2][4];
#pragma unroll
            for (int i = 0; i < 2; i++) {
                const int mb = wm + i * 16;
                float f0 = As[kk + tg][mb + g];
                float f1 = As[kk + tg][mb + g + 8];
                float f2 = As[kk + tg + 4][mb + g];
                float f3 = As[kk + tg + 4][mb + g + 8];
                ah[i][0] = tf32_hi(f0); al[i][0] = tf32_lo(f0, ah[i][0]);
                ah[i][1] = tf32_hi(f1); al[i][1] = tf32_lo(f1, ah[i][1]);
                ah[i][2] = tf32_hi(f2); al[i][2] = tf32_lo(f2, ah[i][2]);
                ah[i][3] = tf32_hi(f3); al[i][3] = tf32_lo(f3, ah[i][3]);
            }
            u32 bh[4][2], bl[4][2];
#pragma unroll
            for (int j = 0; j < 4; j++) {
                const int nb = wn + j * 8;
                float f0 = Ws[kk + tg][nb + g];
                float f1 = Ws[kk + tg + 4][nb + g];
                bh[j][0] = tf32_hi(f0); bl[j][0] = tf32_lo(f0, bh[j][0]);
                bh[j][1] = tf32_hi(f1); bl[j][1] = tf32_lo(f1, bh[j][1]);
            }
#pragma unroll
            for (int i = 0; i < 2; i++)
#pragma unroll
                for (int j = 0; j < 4; j++) {
                    float* c = acc[i][j];
                    mma_tf32(c[0], c[1], c[2], c[3],
                             ah[i][0], ah[i][1], ah[i][2], ah[i][3],
                             bh[j][0], bh[j][1]);
                    mma_tf32(c[0], c[1], c[2], c[3],
                             al[i][0], al[i][1], al[i][2], al[i][3],
                             bh[j][0], bh[j][1]);
                    mma_tf32(c[0], c[1], c[2], c[3],
                             ah[i][0], ah[i][1], ah[i][2], ah[i][3],
                             bl[j][0], bl[j][1]);
                }
        }
    }

#pragma unroll
    for (int i = 0; i < 2; i++)
#pragma unroll
        for (int j = 0; j < 4; j++) {
            const int row = m0 + wm + i * 16 + g;
            const int col = n0 + wn + j * 8 + 2 * tg;
            float2 r0 = make_float2(acc[i][j][0], acc[i][j][1]);
            float2 r1 = make_float2(acc[i][j][2], acc[i][j][3]);
            *(float2*)&Cb[(long)row * N + col] = r0;
            *(float2*)&Cb[(long)(row + 8) * N + col] = r1;
        }
}

// ---------------------------------------------------------------------------
// Tensor-core projection GEMM, K=128. Fused concat+transpose store.
// ---------------------------------------------------------------------------
__global__ __launch_bounds__(256) void gemm_proj_mma(
    const float* __restrict__ A, long aBatch,
    const float* __restrict__ W,
    const float* __restrict__ bias,
    float* __restrict__ out, int coff)
{
    __shared__ float As[128][36];   // [m][k]
    __shared__ float Ws[32][68];    // [k][n]

    const int tid = threadIdx.x;
    const int wid = tid >> 5;
    const int lane = tid & 31;
    const int g = lane >> 2;
    const int tg = lane & 3;
    const int m0 = blockIdx.x * 128;
    const int n0 = blockIdx.y * 64;
    const int wm = (wid & 3) * 32;
    const int wn = (wid >> 2) * 32;
    const float* Ab = A + (long)blockIdx.z * aBatch;

    float acc[2][4][4];
#pragma unroll
    for (int i = 0; i < 2; i++)
#pragma unroll
        for (int j = 0; j < 4; j++)
#pragma unroll
            for (int c = 0; c < 4; c++) acc[i][j][c] = 0.f;

    for (int k0 = 0; k0 < 128; k0 += 32) {
        float4 av[4], wv[2];
#pragma unroll
        for (int p = 0; p < 4; p++) {
            const int idx = tid + 256 * p;
            av[p] = *(const float4*)&Ab[(long)(m0 + (idx >> 3)) * 128 + k0 + (idx & 7) * 4];
        }
#pragma unroll
        for (int p = 0; p < 2; p++) {
            const int idx = tid + 256 * p;
            wv[p] = *(const float4*)&W[(long)(k0 + (idx >> 4)) * 128 + n0 + (idx & 15) * 4];
        }
        __syncthreads();
#pragma unroll
        for (int p = 0; p < 4; p++) {
            const int idx = tid + 256 * p;
            *(float4*)&As[idx >> 3][(idx & 7) * 4] = av[p];
        }
#pragma unroll
        for (int p = 0; p < 2; p++) {
            const int idx = tid + 256 * p;
            *(float4*)&Ws[idx >> 4][(idx & 15) * 4] = wv[p];
        }
        __syncthreads();

#pragma unroll
        for (int ks = 0; ks < 4; ks++) {
            const int kk = ks * 8;
            u32 ah[2][4], al[2][4];
#pragma unroll
            for (int i = 0; i < 2; i++) {
                const int mb = wm + i * 16;
                float f0 = As[mb + g][kk + tg];
                float f1 = As[mb + g + 8][kk + tg];
                float f2 = As[mb + g][kk + tg + 4];
                float f3 = As[mb + g + 8][kk + tg + 4];
                ah[i][0] = tf32_hi(f0); al[i][0] = tf32_lo(f0, ah[i][0]);
                ah[i][1] = tf32_hi(f1); al[i][1] = tf32_lo(f1, ah[i][1]);
                ah[i][2] = tf32_hi(f2); al[i][2] = tf32_lo(f2, ah[i][2]);
                ah[i][3] = tf32_hi(f3); al[i][3] = tf32_lo(f3, ah[i][3]);
            }
            u32 bh[4][2], bl[4][2];
#pragma unroll
            for (int j = 0; j < 4; j++) {
                const int nb = wn + j * 8;
                float f0 = Ws[kk + tg][nb + g];
                float f1 = Ws[kk + tg + 4][nb + g];
                bh[j][0] = tf32_hi(f0); bl[j][0] = tf32_lo(f0, bh[j][0]);
                bh[j][1] = tf32_hi(f1); bl[j][1] = tf32_lo(f1, bh[j][1]);
            }
#pragma unroll
            for (int i = 0; i < 2; i++)
#pragma unroll
                for (int j = 0; j < 4; j++) {
                    float* c = acc[i][j];
                    mma_tf32(c[0], c[1], c[2], c[3],
                             ah[i][0], ah[i][1], ah[i][2], ah[i][3],
                             bh[j][0], bh[j][1]);
                    mma_tf32(c[0], c[1], c[2], c[3],
                             al[i][0], al[i][1], al[i][2], al[i][3],
                             bh[j][0], bh[j][1]);
                    mma_tf32(c[0], c[1], c[2], c[3],
                             ah[i][0], ah[i][1], ah[i][2], ah[i][3],
                             bl[j][0], bl[j][1]);
                }
        }
    }

    float* ob = out + ((long)blockIdx.z * 256 + coff) * 4096;
#pragma unroll
    for (int j = 0; j < 4; j++) {
        const int nl = n0 + wn + j * 8 + 2 * tg;
        const float bv0 = bias[nl];
        const float bv1 = bias[nl + 1];
#pragma unroll
        for (int i = 0; i < 2; i++) {
            const int m = m0 + wm + i * 16 + g;
            ob[(long)nl * 4096 + m]           = acc[i][j][0] + bv0;
            ob[(long)(nl + 1) * 4096 + m]     = acc[i][j][1] + bv1;
            ob[(long)nl * 4096 + m + 8]       = acc[i][j][2] + bv0;
            ob[(long)(nl + 1) * 4096 + m + 8] = acc[i][j][3] + bv1;
        }
    }
}

// ---------------------------------------------------------------------------
// 2x2 average pool, reading x [b][c][64][64] -> g_pool [b][c][1024]
// ---------------------------------------------------------------------------
__global__ __launch_bounds__(256) void pool_kernel(const float* __restrict__ x)
{
    const int bc = blockIdx.x;                 // b*256 + c
    const float* xp = x + (long)bc * 4096;
    float* pp = g_pool + (long)bc * 1024;
    for (int m = threadIdx.x; m < 1024; m += 256) {
        const int hg = m >> 5, wg = m & 31;
        const float* r0 = xp + (hg * 2) * 64 + wg * 2;
        pp[m] = 0.25f * (r0[0] + r0[1] + r0[64] + r0[65]);
    }
}

// ---------------------------------------------------------------------------
// hifi window attention: one warp per (b, window, head). lane = head dim.
// ---------------------------------------------------------------------------
__global__ __launch_bounds__(256) void hifi_attn()
{
    const int wid = (blockIdx.x * blockDim.x + threadIdx.x) >> 5;
    const int lane = threadIdx.x & 31;
    const int head = wid & 3;
    const int win = (wid >> 2) & 1023;
    const int b = wid >> 12;
    const int hg = win >> 5, wgc = win & 31;

    float q[4], k[4], v[4];
    int t[4];
#pragma unroll
    for (int i = 0; i < 4; i++) {
        const int r = 2 * hg + (i >> 1);
        const int c = 2 * wgc + (i & 1);
        t[i] = r * 64 + c;
        const float* base = g_qkv + (long)(b * NTOK + t[i]) * 384 + head * 32 + lane;
        q[i] = base[0];
        k[i] = base[128];
        v[i] = base[256];
    }
    float s[4][4];
#pragma unroll
    for (int i = 0; i < 4; i++)
#pragma unroll
        for (int j = 0; j < 4; j++) {
            float p = q[i] * k[j];
#pragma unroll
            for (int off = 16; off; off >>= 1)
                p += __shfl_xor_sync(0xffffffffu, p, off);
            s[i][j] = p * ATTN_SCALE;
        }
#pragma unroll
    for (int i = 0; i < 4; i++) {
        float mx = fmaxf(fmaxf(s[i][0], s[i][1]), fmaxf(s[i][2], s[i][3]));
        float e0 = __expf(s[i][0] - mx);
        float e1 = __expf(s[i][1] - mx);
        float e2 = __expf(s[i][2] - mx);
        float e3 = __expf(s[i][3] - mx);
        float inv = 1.0f / (e0 + e1 + e2 + e3);
        float o = (e0 * v[0] + e1 * v[1] + e2 * v[2] + e3 * v[3]) * inv;
        g_oh[(long)(b * NTOK + t[i]) * 128 + head * 32 + lane] = o;
    }
}

// ---------------------------------------------------------------------------
// lofi flash attention on tensor cores (bf16x3, m16n8k16).
// Block: 256 thr (8 warps), 128 q-rows per CTA (16 per warp).
// KV chunked by 64; K staged as bf16 hi/lo [64][40], V transposed bf16 hi/lo
// [32][72]. Score C-fragments feed PV A-fragments directly (FA2 layout).
// ---------------------------------------------------------------------------
__global__ __launch_bounds__(256, 2) void lofi_attn_mma()
{
    __shared__ __nv_bfloat16 sKhi[64][40];
    __shared__ __nv_bfloat16 sKlo[64][40];
    __shared__ __nv_bfloat16 sVhi[32][72];
    __shared__ __nv_bfloat16 sVlo[32][72];

    const int tid = threadIdx.x;
    const int lane = tid & 31;
    const int warp = tid >> 5;
    const int g = lane >> 2;        // group row 0..7
    const int tg = lane & 3;        // thread in group
    const int bh = blockIdx.y;      // 0..31
    const int b = bh >> 2, head = bh & 3;
    const int qrow0 = blockIdx.x * 128 + warp * 16;

    // --- Q fragments (loop-invariant), pre-scaled, bf16 hi/lo split ---
    const float* qbase = g_ql + ((long)(b * NTOK + qrow0)) * 128 + head * 32;
    u32 qa_hi[2][4], qa_lo[2][4];   // [ktile(16)][frag reg]
#pragma unroll
    for (int kt = 0; kt < 2; kt++) {
        float2 f0 = *(const float2*)&qbase[(long)g * 128 + kt * 16 + 2 * tg];
        float2 f1 = *(const float2*)&qbase[(long)(g + 8) * 128 + kt * 16 + 2 * tg];
        float2 f2 = *(const float2*)&qbase[(long)g * 128 + kt * 16 + 8 + 2 * tg];
        float2 f3 = *(const float2*)&qbase[(long)(g + 8) * 128 + kt * 16 + 8 + 2 * tg];
        bf16_split2(f0.x * ATTN_SCALE, f0.y * ATTN_SCALE, qa_hi[kt][0], qa_lo[kt][0]);
        bf16_split2(f1.x * ATTN_SCALE, f1.y * ATTN_SCALE, qa_hi[kt][1], qa_lo[kt][1]);
        bf16_split2(f2.x * ATTN_SCALE, f2.y * ATTN_SCALE, qa_hi[kt][2], qa_lo[kt][2]);
        bf16_split2(f3.x * ATTN_SCALE, f3.y * ATTN_SCALE, qa_hi[kt][3], qa_lo[kt][3]);
    }

    float od[4][4];                 // output frags: [d-tile][c0..3]
#pragma unroll
    for (int dt = 0; dt < 4; dt++)
#pragma unroll
        for (int c = 0; c < 4; c++) od[dt][c] = 0.f;
    float mrow[2] = {-1e30f, -1e30f};
    float lrow[2] = {0.f, 0.f};

    const float* kvb = g_kvl + (long)b * MPOOL * 256 + head * 32;

    for (int j0 = 0; j0 < MPOOL; j0 += 64) {
        __syncthreads();
        // stage K (hi/lo) and V (transposed hi/lo)
#pragma unroll
        for (int p = 0; p < 2; p++) {
            const int idx = tid + 256 * p;
            const int r = idx >> 3;           // kv row 0..63
            const int c4 = (idx & 7) * 4;     // dim 0..28
            const float* row = &kvb[(long)(j0 + r) * 256];
            float4 kf = *(const float4*)&row[c4];
            u32 h0, l0, h1, l1;
            bf16_split2(kf.x, kf.y, h0, l0);
            bf16_split2(kf.z, kf.w, h1, l1);
            *(u32*)&sKhi[r][c4]     = h0;
            *(u32*)&sKhi[r][c4 + 2] = h1;
            *(u32*)&sKlo[r][c4]     = l0;
            *(u32*)&sKlo[r][c4 + 2] = l1;
            float4 vf = *(const float4*)&row[128 + c4];
#pragma unroll
            for (int i = 0; i < 4; i++) {
                float v = (&vf.x)[i];
                __nv_bfloat16 vh = __float2bfloat16(v);
                sVhi[c4 + i][r] = vh;
                sVlo[c4 + i][r] = __float2bfloat16(v - __bfloat162float(vh));
            }
        }
        __syncthreads();

        // --- QK^T: 8 n-tiles of 8 kv cols, bf16x3 ---
        float s[8][4];
#pragma unroll
        for (int nt = 0; nt < 8; nt++) {
            float c[4] = {0.f, 0.f, 0.f, 0.f};
            const int kv = nt * 8 + g;
#pragma unroll
            for (int kt = 0; kt < 2; kt++) {
                const int kk = kt * 16;
                u32 bh0 = *(const u32*)&sKhi[kv][kk + 2 * tg];
                u32 bh1 = *(const u32*)&sKhi[kv][kk + 8 + 2 * tg];
                u32 bl0 = *(const u32*)&sKlo[kv][kk + 2 * tg];
                u32 bl1 = *(const u32*)&sKlo[kv][kk + 8 + 2 * tg];
                mma_bf16(c, qa_hi[kt], bh0, bh1);
                mma_bf16(c, qa_lo[kt], bh0, bh1);
                mma_bf16(c, qa_hi[kt], bl0, bl1);
            }
            s[nt][0] = c[0]; s[nt][1] = c[1]; s[nt][2] = c[2]; s[nt][3] = c[3];
        }

        // --- online softmax (rows g and g+8) ---
        float mx0 = s[0][0], mx1 = s[0][2];
#pragma unroll
        for (int nt = 0; nt < 8; nt++) {
            mx0 = fmaxf(mx0, fmaxf(s[nt][0], s[nt][1]));
            mx1 = fmaxf(mx1, fmaxf(s[nt][2], s[nt][3]));
        }
        mx0 = fmaxf(mx0, __shfl_xor_sync(0xffffffffu, mx0, 1));
        mx0 = fmaxf(mx0, __shfl_xor_sync(0xffffffffu, mx0, 2));
        mx1 = fmaxf(mx1, __shfl_xor_sync(0xffffffffu, mx1, 1));
        mx1 = fmaxf(mx1, __shfl_xor_sync(0xffffffffu, mx1, 2));

        const float mn0 = fmaxf(mrow[0], mx0);
        const float mn1 = fmaxf(mrow[1], mx1);
        const float sf0 = __expf(mrow[0] - mn0);
        const float sf1 = __expf(mrow[1] - mn1);
        mrow[0] = mn0; mrow[1] = mn1;
        lrow[0] *= sf0; lrow[1] *= sf1;
#pragma unroll
        for (int dt = 0; dt < 4; dt++) {
            od[dt][0] *= sf0; od[dt][1] *= sf0;
            od[dt][2] *= sf1; od[dt][3] *= sf1;
        }
#pragma unroll
        for (int nt = 0; nt < 8; nt++) {
            s[nt][0] = __expf(s[nt][0] - mn0);
            s[nt][1] = __expf(s[nt][1] - mn0);
            s[nt][2] = __expf(s[nt][2] - mn1);
            s[nt][3] = __expf(s[nt][3] - mn1);
            lrow[0] += s[nt][0] + s[nt][1];
            lrow[1] += s[nt][2] + s[nt][3];
        }

        // --- PV: 4 k-tiles of 16 kv, 4 d-tiles of 8, bf16x3 ---
#pragma unroll
        for (int kt2 = 0; kt2 < 4; kt2++) {
            u32 pa_hi[4], pa_lo[4];
            // A frag from score tiles 2*kt2 (k-cols 0-7) and 2*kt2+1 (8-15)
            bf16_split2(s[2 * kt2][0],     s[2 * kt2][1],     pa_hi[0], pa_lo[0]);
            bf16_split2(s[2 * kt2][2],     s[2 * kt2][3],     pa_hi[1], pa_lo[1]);
            bf16_split2(s[2 * kt2 + 1][0], s[2 * kt2 + 1][1], pa_hi[2], pa_lo[2]);
            bf16_split2(s[2 * kt2 + 1][2], s[2 * kt2 + 1][3], pa_hi[3], pa_lo[3]);
            const int kv0 = kt2 * 16;
#pragma unroll
            for (int dt = 0; dt < 4; dt++) {
                const int d = dt * 8 + g;
                u32 vb_h0 = *(const u32*)&sVhi[d][kv0 + 2 * tg];
                u32 vb_h1 = *(const u32*)&sVhi[d][kv0 + 8 + 2 * tg];
                u32 vb_l0 = *(const u32*)&sVlo[d][kv0 + 2 * tg];
                u32 vb_l1 = *(const u32*)&sVlo[d][kv0 + 8 + 2 * tg];
                mma_bf16(od[dt], pa_hi, vb_h0, vb_h1);
                mma_bf16(od[dt], pa_lo, vb_h0, vb_h1);
                mma_bf16(od[dt], pa_hi, vb_l0, vb_l1);
            }
        }
    }

    // reduce l across the quad (each thread held 16 of 64 cols per chunk)
    lrow[0] += __shfl_xor_sync(0xffffffffu, lrow[0], 1);
    lrow[0] += __shfl_xor_sync(0xffffffffu, lrow[0], 2);
    lrow[1] += __shfl_xor_sync(0xffffffffu, lrow[1], 1);
    lrow[1] += __shfl_xor_sync(0xffffffffu, lrow[1], 2);
    const float inv0 = 1.0f / lrow[0];
    const float inv1 = 1.0f / lrow[1];

    float* ob = g_ol + ((long)(b * NTOK + qrow0)) * 128 + head * 32;
#pragma unroll
    for (int dt = 0; dt < 4; dt++) {
        const int col = dt * 8 + 2 * tg;
        *(float2*)&ob[(long)g * 128 + col] =
            make_float2(od[dt][0] * inv0, od[dt][1] * inv0);
        *(float2*)&ob[(long)(g + 8) * 128 + col] =
            make_float2(od[dt][2] * inv1, od[dt][3] * inv1);
    }
}

// ---------------------------------------------------------------------------
extern "C" void kernel_launch(void* const* d_in, const int* in_sizes, int n_in,
                              void* d_out, int out_size)
{
    const float* x        = (const float*)d_in[0];
    const float* l_q_w    = (const float*)d_in[1];
    const float* l_kv_w   = (const float*)d_in[2];
    const float* l_proj_w = (const float*)d_in[3];
    const float* l_proj_b = (const float*)d_in[4];
    const float* h_qkv_w  = (const float*)d_in[5];
    const float* h_proj_w = (const float*)d_in[6];
    const float* h_proj_b = (const float*)d_in[7];
    float* out = (float*)d_out;

    float *qkv, *ql, *pool, *kvl, *oh, *ol;
    cudaGetSymbolAddress((void**)&qkv,  g_qkv);
    cudaGetSymbolAddress((void**)&ql,   g_ql);
    cudaGetSymbolAddress((void**)&pool, g_pool);
    cudaGetSymbolAddress((void**)&kvl,  g_kvl);
    cudaGetSymbolAddress((void**)&oh,   g_oh);
    cudaGetSymbolAddress((void**)&ol,   g_ol);

    // hifi qkv: x^T @ h_qkv_w -> [b][4096][384]
    gemm_xt_mma<<<dim3(32, 6, 8), 256>>>(x, (long)CDIM * NTOK, h_qkv_w,
                                         qkv, (long)NTOK * 384, NTOK, 384);
    // lofi q: x^T @ l_q_w -> [b][4096][128]
    gemm_xt_mma<<<dim3(32, 2, 8), 256>>>(x, (long)CDIM * NTOK, l_q_w,
                                         ql, (long)NTOK * 128, NTOK, 128);
    // 2x2 avg pool -> [b][c][1024]
    pool_kernel<<<BB * CDIM, 256>>>(x);
    // lofi kv: pooled^T @ l_kv_w -> [b][1024][256]
    gemm_xt_mma<<<dim3(8, 4, 8), 256>>>(pool, (long)CDIM * MPOOL, l_kv_w,
                                        kvl, (long)MPOOL * 256, MPOOL, 256);
    // hifi window attention
    hifi_attn<<<4096, 256>>>();
    // lofi flash attention (tensor cores)
    lofi_attn_mma<<<dim3(32, 32), 256>>>();
    // projections, fused concat+transpose into output
    gemm_proj_mma<<<dim3(32, 2, 8), 256>>>(oh, (long)NTOK * 128, h_proj_w, h_proj_b,
                                           out, 0);
    gemm_proj_mma<<<dim3(32, 2, 8), 256>>>(ol, (long)NTOK * 128, l_proj_w, l_proj_b,
                                           out, 128);
}

// round 7
// speedup vs baseline: 2.7571x; 1.3637x over previous
#include <cuda_runtime.h>
#include <cuda_bf16.h>

// ---------------------------------------------------------------------------
// HiLo attention, b=8, dim=256, H=W=64, WS=2, 4+4 heads, head_dim=32
// Round 7: GEMMs rewritten as bf16x3 (m16n8k16) with staging-time hi/lo split,
// ldmatrix fragment loads and software-pipelined gmem loads.
// lofi attention: R6 tensor-core flash kernel (unchanged).
// ---------------------------------------------------------------------------

#define BB 8
#define CDIM 256
#define NTOK 4096          // 64*64 tokens per batch
#define MPOOL 1024         // 32*32 pooled tokens per batch
#define ATTN_SCALE 0.17677669529663687f   // 32^-0.5

typedef unsigned long long u64;
typedef unsigned int u32;

// scratch (device globals; ~117 MB total)
__device__ float g_qkv [BB * NTOK * 384];   // hifi qkv  [b][t][s*128+head*32+d]
__device__ float g_ql  [BB * NTOK * 128];   // lofi q    [b][t][head*32+d]
__device__ float g_pool[BB * CDIM * MPOOL]; // pooled    [b][c][m]  (K-major)
__device__ float g_kvl [BB * MPOOL * 256];  // lofi kv   [b][m][s*128+head*32+d]
__device__ float g_oh  [BB * NTOK * 128];   // hifi attn out
__device__ float g_ol  [BB * NTOK * 128];   // lofi attn out

// ---- bf16 helpers ----------------------------------------------------------
__device__ __forceinline__ void mma_bf16(
    float* c, const u32* a, u32 b0, u32 b1)
{
    asm volatile(
        "mma.sync.aligned.m16n8k16.row.col.f32.bf16.bf16.f32 "
        "{%0,%1,%2,%3}, {%4,%5,%6,%7}, {%8,%9}, {%0,%1,%2,%3};\n"
        : "+f"(c[0]), "+f"(c[1]), "+f"(c[2]), "+f"(c[3])
        : "r"(a[0]), "r"(a[1]), "r"(a[2]), "r"(a[3]), "r"(b0), "r"(b1));
}
// split two floats into packed bf16x2 hi + residual bf16x2 lo
// packed layout: low half = x0, high half = x1
__device__ __forceinline__ void bf16_split2(float x0, float x1, u32& hi, u32& lo)
{
    asm("cvt.rn.bf16x2.f32 %0, %1, %2;" : "=r"(hi) : "f"(x1), "f"(x0));
    float h0 = __uint_as_float(hi << 16);
    float h1 = __uint_as_float(hi & 0xffff0000u);
    asm("cvt.rn.bf16x2.f32 %0, %1, %2;" : "=r"(lo) : "f"(x1 - h1), "f"(x0 - h0));
}
__device__ __forceinline__ u32 s2u(const void* p) {
    return (u32)__cvta_generic_to_shared(p);
}
__device__ __forceinline__ void ldsm_x4_t(u32& r0, u32& r1, u32& r2, u32& r3, u32 addr)
{
    asm volatile("ldmatrix.sync.aligned.m8n8.x4.trans.shared.b16 "
                 "{%0,%1,%2,%3}, [%4];"
                 : "=r"(r0), "=r"(r1), "=r"(r2), "=r"(r3) : "r"(addr));
}
__device__ __forceinline__ void ldsm_x4(u32& r0, u32& r1, u32& r2, u32& r3, u32 addr)
{
    asm volatile("ldmatrix.sync.aligned.m8n8.x4.shared.b16 "
                 "{%0,%1,%2,%3}, [%4];"
                 : "=r"(r0), "=r"(r1), "=r"(r2), "=r"(r3) : "r"(addr));
}

// ---------------------------------------------------------------------------
// bf16x3 GEMM, A K-major: C[b][m][n] = sum_k A[b][k][m] * W[k][n], K=256.
// BM=128, BN=64, BK=32, 256 thr (8 warps: 4 m x 2 n).
// hi/lo split done at staging; fragments via ldmatrix.trans.
// ---------------------------------------------------------------------------
__global__ __launch_bounds__(256, 2) void gemm_xt_bf16(
    const float* __restrict__ A, long aBatch,
    const float* __restrict__ W,
    float* __restrict__ Cout, long cBatch,
    int M, int N)
{
    __shared__ __nv_bfloat16 Ahi[32][136], Alo[32][136];   // [k][m], pad 8
    __shared__ __nv_bfloat16 Whi[32][72],  Wlo[32][72];    // [k][n], pad 8

    const int tid = threadIdx.x;
    const int wid = tid >> 5;
    const int lane = tid & 31;
    const int m0 = blockIdx.x * 128;
    const int n0 = blockIdx.y * 64;
    const int wm = (wid & 3) * 32;
    const int wn = (wid >> 2) * 32;
    const float* Ab = A + (long)blockIdx.z * aBatch;
    float* Cb = Cout + (long)blockIdx.z * cBatch;

    // ldmatrix lane offsets
    const int l7 = lane & 7;
    const int a_koff = l7 + ((lane & 16) ? 8 : 0);   // A trans: r0 (k0-7,m0-7) r1 (k0-7,m8-15) r2 (k8,m0) r3 (k8,m8)
    const int a_moff = (lane & 8) ? 8 : 0;
    const int b_koff = l7 + ((lane & 8) ? 8 : 0);    // B trans: r0/r1 = n-tile0 b0/b1, r2/r3 = n-tile1
    const int b_noff = (lane & 16) ? 8 : 0;

    float acc[2][4][4];
#pragma unroll
    for (int i = 0; i < 2; i++)
#pragma unroll
        for (int j = 0; j < 4; j++)
#pragma unroll
            for (int c = 0; c < 4; c++) acc[i][j][c] = 0.f;

    float4 av[4], wv[2];
    // prologue loads (chunk 0)
#pragma unroll
    for (int p = 0; p < 4; p++) {
        const int idx = tid + 256 * p;
        av[p] = *(const float4*)&Ab[(long)(idx >> 5) * M + m0 + (idx & 31) * 4];
    }
#pragma unroll
    for (int p = 0; p < 2; p++) {
        const int idx = tid + 256 * p;
        wv[p] = *(const float4*)&W[(long)(idx >> 4) * N + n0 + (idx & 15) * 4];
    }

    for (int k0 = 0; k0 < 256; k0 += 32) {
        __syncthreads();
        // stage (split to bf16 hi/lo, pairs packed along m / n)
#pragma unroll
        for (int p = 0; p < 4; p++) {
            const int idx = tid + 256 * p;
            const int kr = idx >> 5, mc = (idx & 31) * 4;
            u32 h01, l01, h23, l23;
            bf16_split2(av[p].x, av[p].y, h01, l01);
            bf16_split2(av[p].z, av[p].w, h23, l23);
            *(u32*)&Ahi[kr][mc] = h01; *(u32*)&Ahi[kr][mc + 2] = h23;
            *(u32*)&Alo[kr][mc] = l01; *(u32*)&Alo[kr][mc + 2] = l23;
        }
#pragma unroll
        for (int p = 0; p < 2; p++) {
            const int idx = tid + 256 * p;
            const int kr = idx >> 4, nc = (idx & 15) * 4;
            u32 h01, l01, h23, l23;
            bf16_split2(wv[p].x, wv[p].y, h01, l01);
            bf16_split2(wv[p].z, wv[p].w, h23, l23);
            *(u32*)&Whi[kr][nc] = h01; *(u32*)&Whi[kr][nc + 2] = h23;
            *(u32*)&Wlo[kr][nc] = l01; *(u32*)&Wlo[kr][nc + 2] = l23;
        }
        __syncthreads();

        // prefetch next chunk
        if (k0 + 32 < 256) {
#pragma unroll
            for (int p = 0; p < 4; p++) {
                const int idx = tid + 256 * p;
                av[p] = *(const float4*)&Ab[(long)(k0 + 32 + (idx >> 5)) * M + m0 + (idx & 31) * 4];
            }
#pragma unroll
            for (int p = 0; p < 2; p++) {
                const int idx = tid + 256 * p;
                wv[p] = *(const float4*)&W[(long)(k0 + 32 + (idx >> 4)) * N + n0 + (idx & 15) * 4];
            }
        }

#pragma unroll
        for (int ks = 0; ks < 2; ks++) {
            const int kk = ks * 16;
            u32 ahi[2][4], alo[2][4];
#pragma unroll
            for (int i = 0; i < 2; i++) {
                const int mb = wm + i * 16;
                ldsm_x4_t(ahi[i][0], ahi[i][1], ahi[i][2], ahi[i][3],
                          s2u(&Ahi[kk + a_koff][mb + a_moff]));
                ldsm_x4_t(alo[i][0], alo[i][1], alo[i][2], alo[i][3],
                          s2u(&Alo[kk + a_koff][mb + a_moff]));
            }
            u32 bhi[4][2], blo[4][2];
#pragma unroll
            for (int np = 0; np < 2; np++) {
                const int nb = wn + np * 16;
                u32 r0, r1, r2, r3;
                ldsm_x4_t(r0, r1, r2, r3, s2u(&Whi[kk + b_koff][nb + b_noff]));
                bhi[2 * np][0] = r0; bhi[2 * np][1] = r1;
                bhi[2 * np + 1][0] = r2; bhi[2 * np + 1][1] = r3;
                ldsm_x4_t(r0, r1, r2, r3, s2u(&Wlo[kk + b_koff][nb + b_noff]));
                blo[2 * np][0] = r0; blo[2 * np][1] = r1;
                blo[2 * np + 1][0] = r2; blo[2 * np + 1][1] = r3;
            }
#pragma unroll
            for (int i = 0; i < 2; i++)
#pragma unroll
                for (int j = 0; j < 4; j++) {
                    mma_bf16(acc[i][j], ahi[i], bhi[j][0], bhi[j][1]);
                    mma_bf16(acc[i][j], alo[i], bhi[j][0], bhi[j][1]);
                    mma_bf16(acc[i][j], ahi[i], blo[j][0], blo[j][1]);
                }
        }
    }

    const int g = lane >> 2, tg = lane & 3;
#pragma unroll
    for (int i = 0; i < 2; i++)
#pragma unroll
        for (int j = 0; j < 4; j++) {
            const int row = m0 + wm + i * 16 + g;
            const int col = n0 + wn + j * 8 + 2 * tg;
            *(float2*)&Cb[(long)row * N + col] =
                make_float2(acc[i][j][0], acc[i][j][1]);
            *(float2*)&Cb[(long)(row + 8) * N + col] =
                make_float2(acc[i][j][2], acc[i][j][3]);
        }
}

// ---------------------------------------------------------------------------
// bf16x3 projection GEMM, K=128: out[(b*256+coff+n)*4096+m] = bias[n] + A@W
// A row-major [M][128]. Fused concat+transpose store.
// ---------------------------------------------------------------------------
__global__ __launch_bounds__(256, 2) void gemm_proj_bf16(
    const float* __restrict__ A, long aBatch,
    const float* __restrict__ W,
    const float* __restrict__ bias,
    float* __restrict__ out, int coff)
{
    __shared__ __nv_bfloat16 Ahi[128][40], Alo[128][40];   // [m][k], pad 8
    __shared__ __nv_bfloat16 Whi[32][72],  Wlo[32][72];    // [k][n], pad 8

    const int tid = threadIdx.x;
    const int wid = tid >> 5;
    const int lane = tid & 31;
    const int m0 = blockIdx.x * 128;
    const int n0 = blockIdx.y * 64;
    const int wm = (wid & 3) * 32;
    const int wn = (wid >> 2) * 32;
    const float* Ab = A + (long)blockIdx.z * aBatch;

    const int l7 = lane & 7;
    const int a_moff = l7 + ((lane & 8) ? 8 : 0);     // A non-trans on [m][k]
    const int a_koff = (lane & 16) ? 8 : 0;
    const int b_koff = l7 + ((lane & 8) ? 8 : 0);
    const int b_noff = (lane & 16) ? 8 : 0;

    float acc[2][4][4];
#pragma unroll
    for (int i = 0; i < 2; i++)
#pragma unroll
        for (int j = 0; j < 4; j++)
#pragma unroll
            for (int c = 0; c < 4; c++) acc[i][j][c] = 0.f;

    float4 av[4], wv[2];
#pragma unroll
    for (int p = 0; p < 4; p++) {
        const int idx = tid + 256 * p;
        av[p] = *(const float4*)&Ab[(long)(m0 + (idx >> 3)) * 128 + (idx & 7) * 4];
    }
#pragma unroll
    for (int p = 0; p < 2; p++) {
        const int idx = tid + 256 * p;
        wv[p] = *(const float4*)&W[(long)(idx >> 4) * 128 + n0 + (idx & 15) * 4];
    }

    for (int k0 = 0; k0 < 128; k0 += 32) {
        __syncthreads();
#pragma unroll
        for (int p = 0; p < 4; p++) {
            const int idx = tid + 256 * p;
            const int mr = idx >> 3, kc = (idx & 7) * 4;
            u32 h01, l01, h23, l23;
            bf16_split2(av[p].x, av[p].y, h01, l01);   // pairs along k
            bf16_split2(av[p].z, av[p].w, h23, l23);
            *(u32*)&Ahi[mr][kc] = h01; *(u32*)&Ahi[mr][kc + 2] = h23;
            *(u32*)&Alo[mr][kc] = l01; *(u32*)&Alo[mr][kc + 2] = l23;
        }
#pragma unroll
        for (int p = 0; p < 2; p++) {
            const int idx = tid + 256 * p;
            const int kr = idx >> 4, nc = (idx & 15) * 4;
            u32 h01, l01, h23, l23;
            bf16_split2(wv[p].x, wv[p].y, h01, l01);   // pairs along n
            bf16_split2(wv[p].z, wv[p].w, h23, l23);
            *(u32*)&Whi[kr][nc] = h01; *(u32*)&Whi[kr][nc + 2] = h23;
            *(u32*)&Wlo[kr][nc] = l01; *(u32*)&Wlo[kr][nc + 2] = l23;
        }
        __syncthreads();

        if (k0 + 32 < 128) {
#pragma unroll
            for (int p = 0; p < 4; p++) {
                const int idx = tid + 256 * p;
                av[p] = *(const float4*)&Ab[(long)(m0 + (idx >> 3)) * 128 + k0 + 32 + (idx & 7) * 4];
            }
#pragma unroll
            for (int p = 0; p < 2; p++) {
                const int idx = tid + 256 * p;
                wv[p] = *(const float4*)&W[(long)(k0 + 32 + (idx >> 4)) * 128 + n0 + (idx & 15) * 4];
            }
        }

#pragma unroll
        for (int ks = 0; ks < 2; ks++) {
            const int kk = ks * 16;
            u32 ahi[2][4], alo[2][4];
#pragma unroll
            for (int i = 0; i < 2; i++) {
                const int mb = wm + i * 16;
                ldsm_x4(ahi[i][0], ahi[i][1], ahi[i][2], ahi[i][3],
                        s2u(&Ahi[mb + a_moff][kk + a_koff]));
                ldsm_x4(alo[i][0], alo[i][1], alo[i][2], alo[i][3],
                        s2u(&Alo[mb + a_moff][kk + a_koff]));
            }
            u32 bhi[4][2], blo[4][2];
#pragma unroll
            for (int np = 0; np < 2; np++) {
                const int nb = wn + np * 16;
                u32 r0, r1, r2, r3;
                ldsm_x4_t(r0, r1, r2, r3, s2u(&Whi[kk + b_koff][nb + b_noff]));
                bhi[2 * np][0] = r0; bhi[2 * np][1] = r1;
                bhi[2 * np + 1][0] = r2; bhi[2 * np + 1][1] = r3;
                ldsm_x4_t(r0, r1, r2, r3, s2u(&Wlo[kk + b_koff][nb + b_noff]));
                blo[2 * np][0] = r0; blo[2 * np][1] = r1;
                blo[2 * np + 1][0] = r2; blo[2 * np + 1][1] = r3;
            }
#pragma unroll
            for (int i = 0; i < 2; i++)
#pragma unroll
                for (int j = 0; j < 4; j++) {
                    mma_bf16(acc[i][j], ahi[i], bhi[j][0], bhi[j][1]);
                    mma_bf16(acc[i][j], alo[i], bhi[j][0], bhi[j][1]);
                    mma_bf16(acc[i][j], ahi[i], blo[j][0], blo[j][1]);
                }
        }
    }

    const int g = lane >> 2, tg = lane & 3;
    float* ob = out + ((long)blockIdx.z * 256 + coff) * 4096;
#pragma unroll
    for (int j = 0; j < 4; j++) {
        const int nl = n0 + wn + j * 8 + 2 * tg;
        const float bv0 = bias[nl];
        const float bv1 = bias[nl + 1];
#pragma unroll
        for (int i = 0; i < 2; i++) {
            const int m = m0 + wm + i * 16 + g;
            ob[(long)nl * 4096 + m]           = acc[i][j][0] + bv0;
            ob[(long)(nl + 1) * 4096 + m]     = acc[i][j][1] + bv1;
            ob[(long)nl * 4096 + m + 8]       = acc[i][j][2] + bv0;
            ob[(long)(nl + 1) * 4096 + m + 8] = acc[i][j][3] + bv1;
        }
    }
}

// ---------------------------------------------------------------------------
// 2x2 average pool, reading x [b][c][64][64] -> g_pool [b][c][1024]
// ---------------------------------------------------------------------------
__global__ __launch_bounds__(256) void pool_kernel(const float* __restrict__ x)
{
    const int bc = blockIdx.x;                 // b*256 + c
    const float* xp = x + (long)bc * 4096;
    float* pp = g_pool + (long)bc * 1024;
    for (int m = threadIdx.x; m < 1024; m += 256) {
        const int hg = m >> 5, wg = m & 31;
        const float* r0 = xp + (hg * 2) * 64 + wg * 2;
        pp[m] = 0.25f * (r0[0] + r0[1] + r0[64] + r0[65]);
    }
}

// ---------------------------------------------------------------------------
// hifi window attention: one warp per (b, window, head). lane = head dim.
// ---------------------------------------------------------------------------
__global__ __launch_bounds__(256) void hifi_attn()
{
    const int wid = (blockIdx.x * blockDim.x + threadIdx.x) >> 5;
    const int lane = threadIdx.x & 31;
    const int head = wid & 3;
    const int win = (wid >> 2) & 1023;
    const int b = wid >> 12;
    const int hg = win >> 5, wgc = win & 31;

    float q[4], k[4], v[4];
    int t[4];
#pragma unroll
    for (int i = 0; i < 4; i++) {
        const int r = 2 * hg + (i >> 1);
        const int c = 2 * wgc + (i & 1);
        t[i] = r * 64 + c;
        const float* base = g_qkv + (long)(b * NTOK + t[i]) * 384 + head * 32 + lane;
        q[i] = base[0];
        k[i] = base[128];
        v[i] = base[256];
    }
    float s[4][4];
#pragma unroll
    for (int i = 0; i < 4; i++)
#pragma unroll
        for (int j = 0; j < 4; j++) {
            float p = q[i] * k[j];
#pragma unroll
            for (int off = 16; off; off >>= 1)
                p += __shfl_xor_sync(0xffffffffu, p, off);
            s[i][j] = p * ATTN_SCALE;
        }
#pragma unroll
    for (int i = 0; i < 4; i++) {
        float mx = fmaxf(fmaxf(s[i][0], s[i][1]), fmaxf(s[i][2], s[i][3]));
        float e0 = __expf(s[i][0] - mx);
        float e1 = __expf(s[i][1] - mx);
        float e2 = __expf(s[i][2] - mx);
        float e3 = __expf(s[i][3] - mx);
        float inv = 1.0f / (e0 + e1 + e2 + e3);
        float o = (e0 * v[0] + e1 * v[1] + e2 * v[2] + e3 * v[3]) * inv;
        g_oh[(long)(b * NTOK + t[i]) * 128 + head * 32 + lane] = o;
    }
}

// ---------------------------------------------------------------------------
// lofi flash attention on tensor cores (bf16x3, m16n8k16). (R6, unchanged)
// ---------------------------------------------------------------------------
__global__ __launch_bounds__(256, 2) void lofi_attn_mma()
{
    __shared__ __nv_bfloat16 sKhi[64][40];
    __shared__ __nv_bfloat16 sKlo[64][40];
    __shared__ __nv_bfloat16 sVhi[32][72];
    __shared__ __nv_bfloat16 sVlo[32][72];

    const int tid = threadIdx.x;
    const int lane = tid & 31;
    const int warp = tid >> 5;
    const int g = lane >> 2;
    const int tg = lane & 3;
    const int bh = blockIdx.y;
    const int b = bh >> 2, head = bh & 3;
    const int qrow0 = blockIdx.x * 128 + warp * 16;

    const float* qbase = g_ql + ((long)(b * NTOK + qrow0)) * 128 + head * 32;
    u32 qa_hi[2][4], qa_lo[2][4];
#pragma unroll
    for (int kt = 0; kt < 2; kt++) {
        float2 f0 = *(const float2*)&qbase[(long)g * 128 + kt * 16 + 2 * tg];
        float2 f1 = *(const float2*)&qbase[(long)(g + 8) * 128 + kt * 16 + 2 * tg];
        float2 f2 = *(const float2*)&qbase[(long)g * 128 + kt * 16 + 8 + 2 * tg];
        float2 f3 = *(const float2*)&qbase[(long)(g + 8) * 128 + kt * 16 + 8 + 2 * tg];
        bf16_split2(f0.x * ATTN_SCALE, f0.y * ATTN_SCALE, qa_hi[kt][0], qa_lo[kt][0]);
        bf16_split2(f1.x * ATTN_SCALE, f1.y * ATTN_SCALE, qa_hi[kt][1], qa_lo[kt][1]);
        bf16_split2(f2.x * ATTN_SCALE, f2.y * ATTN_SCALE, qa_hi[kt][2], qa_lo[kt][2]);
        bf16_split2(f3.x * ATTN_SCALE, f3.y * ATTN_SCALE, qa_hi[kt][3], qa_lo[kt][3]);
    }

    float od[4][4];
#pragma unroll
    for (int dt = 0; dt < 4; dt++)
#pragma unroll
        for (int c = 0; c < 4; c++) od[dt][c] = 0.f;
    float mrow[2] = {-1e30f, -1e30f};
    float lrow[2] = {0.f, 0.f};

    const float* kvb = g_kvl + (long)b * MPOOL * 256 + head * 32;

    for (int j0 = 0; j0 < MPOOL; j0 += 64) {
        __syncthreads();
#pragma unroll
        for (int p = 0; p < 2; p++) {
            const int idx = tid + 256 * p;
            const int r = idx >> 3;
            const int c4 = (idx & 7) * 4;
            const float* row = &kvb[(long)(j0 + r) * 256];
            float4 kf = *(const float4*)&row[c4];
            u32 h0, l0, h1, l1;
            bf16_split2(kf.x, kf.y, h0, l0);
            bf16_split2(kf.z, kf.w, h1, l1);
            *(u32*)&sKhi[r][c4]     = h0;
            *(u32*)&sKhi[r][c4 + 2] = h1;
            *(u32*)&sKlo[r][c4]     = l0;
            *(u32*)&sKlo[r][c4 + 2] = l1;
            float4 vf = *(const float4*)&row[128 + c4];
#pragma unroll
            for (int i = 0; i < 4; i++) {
                float v = (&vf.x)[i];
                __nv_bfloat16 vh = __float2bfloat16(v);
                sVhi[c4 + i][r] = vh;
                sVlo[c4 + i][r] = __float2bfloat16(v - __bfloat162float(vh));
            }
        }
        __syncthreads();

        float s[8][4];
#pragma unroll
        for (int nt = 0; nt < 8; nt++) {
            float c[4] = {0.f, 0.f, 0.f, 0.f};
            const int kv = nt * 8 + g;
#pragma unroll
            for (int kt = 0; kt < 2; kt++) {
                const int kk = kt * 16;
                u32 bh0 = *(const u32*)&sKhi[kv][kk + 2 * tg];
                u32 bh1 = *(const u32*)&sKhi[kv][kk + 8 + 2 * tg];
                u32 bl0 = *(const u32*)&sKlo[kv][kk + 2 * tg];
                u32 bl1 = *(const u32*)&sKlo[kv][kk + 8 + 2 * tg];
                mma_bf16(c, qa_hi[kt], bh0, bh1);
                mma_bf16(c, qa_lo[kt], bh0, bh1);
                mma_bf16(c, qa_hi[kt], bl0, bl1);
            }
            s[nt][0] = c[0]; s[nt][1] = c[1]; s[nt][2] = c[2]; s[nt][3] = c[3];
        }

        float mx0 = s[0][0], mx1 = s[0][2];
#pragma unroll
        for (int nt = 0; nt < 8; nt++) {
            mx0 = fmaxf(mx0, fmaxf(s[nt][0], s[nt][1]));
            mx1 = fmaxf(mx1, fmaxf(s[nt][2], s[nt][3]));
        }
        mx0 = fmaxf(mx0, __shfl_xor_sync(0xffffffffu, mx0, 1));
        mx0 = fmaxf(mx0, __shfl_xor_sync(0xffffffffu, mx0, 2));
        mx1 = fmaxf(mx1, __shfl_xor_sync(0xffffffffu, mx1, 1));
        mx1 = fmaxf(mx1, __shfl_xor_sync(0xffffffffu, mx1, 2));

        const float mn0 = fmaxf(mrow[0], mx0);
        const float mn1 = fmaxf(mrow[1], mx1);
        const float sf0 = __expf(mrow[0] - mn0);
        const float sf1 = __expf(mrow[1] - mn1);
        mrow[0] = mn0; mrow[1] = mn1;
        lrow[0] *= sf0; lrow[1] *= sf1;
#pragma unroll
        for (int dt = 0; dt < 4; dt++) {
            od[dt][0] *= sf0; od[dt][1] *= sf0;
            od[dt][2] *= sf1; od[dt][3] *= sf1;
        }
#pragma unroll
        for (int nt = 0; nt < 8; nt++) {
            s[nt][0] = __expf(s[nt][0] - mn0);
            s[nt][1] = __expf(s[nt][1] - mn0);
            s[nt][2] = __expf(s[nt][2] - mn1);
            s[nt][3] = __expf(s[nt][3] - mn1);
            lrow[0] += s[nt][0] + s[nt][1];
            lrow[1] += s[nt][2] + s[nt][3];
        }

#pragma unroll
        for (int kt2 = 0; kt2 < 4; kt2++) {
            u32 pa_hi[4], pa_lo[4];
            bf16_split2(s[2 * kt2][0],     s[2 * kt2][1],     pa_hi[0], pa_lo[0]);
            bf16_split2(s[2 * kt2][2],     s[2 * kt2][3],     pa_hi[1], pa_lo[1]);
            bf16_split2(s[2 * kt2 + 1][0], s[2 * kt2 + 1][1], pa_hi[2], pa_lo[2]);
            bf16_split2(s[2 * kt2 + 1][2], s[2 * kt2 + 1][3], pa_hi[3], pa_lo[3]);
            const int kv0 = kt2 * 16;
#pragma unroll
            for (int dt = 0; dt < 4; dt++) {
                const int d = dt * 8 + g;
                u32 vb_h0 = *(const u32*)&sVhi[d][kv0 + 2 * tg];
                u32 vb_h1 = *(const u32*)&sVhi[d][kv0 + 8 + 2 * tg];
                u32 vb_l0 = *(const u32*)&sVlo[d][kv0 + 2 * tg];
                u32 vb_l1 = *(const u32*)&sVlo[d][kv0 + 8 + 2 * tg];
                mma_bf16(od[dt], pa_hi, vb_h0, vb_h1);
                mma_bf16(od[dt], pa_lo, vb_h0, vb_h1);
                mma_bf16(od[dt], pa_hi, vb_l0, vb_l1);
            }
        }
    }

    lrow[0] += __shfl_xor_sync(0xffffffffu, lrow[0], 1);
    lrow[0] += __shfl_xor_sync(0xffffffffu, lrow[0], 2);
    lrow[1] += __shfl_xor_sync(0xffffffffu, lrow[1], 1);
    lrow[1] += __shfl_xor_sync(0xffffffffu, lrow[1], 2);
    const float inv0 = 1.0f / lrow[0];
    const float inv1 = 1.0f / lrow[1];

    float* ob = g_ol + ((long)(b * NTOK + qrow0)) * 128 + head * 32;
#pragma unroll
    for (int dt = 0; dt < 4; dt++) {
        const int col = dt * 8 + 2 * tg;
        *(float2*)&ob[(long)g * 128 + col] =
            make_float2(od[dt][0] * inv0, od[dt][1] * inv0);
        *(float2*)&ob[(long)(g + 8) * 128 + col] =
            make_float2(od[dt][2] * inv1, od[dt][3] * inv1);
    }
}

// ---------------------------------------------------------------------------
extern "C" void kernel_launch(void* const* d_in, const int* in_sizes, int n_in,
                              void* d_out, int out_size)
{
    const float* x        = (const float*)d_in[0];
    const float* l_q_w    = (const float*)d_in[1];
    const float* l_kv_w   = (const float*)d_in[2];
    const float* l_proj_w = (const float*)d_in[3];
    const float* l_proj_b = (const float*)d_in[4];
    const float* h_qkv_w  = (const float*)d_in[5];
    const float* h_proj_w = (const float*)d_in[6];
    const float* h_proj_b = (const float*)d_in[7];
    float* out = (float*)d_out;

    float *qkv, *ql, *pool, *kvl, *oh, *ol;
    cudaGetSymbolAddress((void**)&qkv,  g_qkv);
    cudaGetSymbolAddress((void**)&ql,   g_ql);
    cudaGetSymbolAddress((void**)&pool, g_pool);
    cudaGetSymbolAddress((void**)&kvl,  g_kvl);
    cudaGetSymbolAddress((void**)&oh,   g_oh);
    cudaGetSymbolAddress((void**)&ol,   g_ol);

    // hifi qkv: x^T @ h_qkv_w -> [b][4096][384]
    gemm_xt_bf16<<<dim3(32, 6, 8), 256>>>(x, (long)CDIM * NTOK, h_qkv_w,
                                          qkv, (long)NTOK * 384, NTOK, 384);
    // lofi q: x^T @ l_q_w -> [b][4096][128]
    gemm_xt_bf16<<<dim3(32, 2, 8), 256>>>(x, (long)CDIM * NTOK, l_q_w,
                                          ql, (long)NTOK * 128, NTOK, 128);
    // 2x2 avg pool -> [b][c][1024]
    pool_kernel<<<BB * CDIM, 256>>>(x);
    // lofi kv: pooled^T @ l_kv_w -> [b][1024][256]
    gemm_xt_bf16<<<dim3(8, 4, 8), 256>>>(pool, (long)CDIM * MPOOL, l_kv_w,
                                         kvl, (long)MPOOL * 256, MPOOL, 256);
    // hifi window attention
    hifi_attn<<<4096, 256>>>();
    // lofi flash attention (tensor cores)
    lofi_attn_mma<<<dim3(32, 32), 256>>>();
    // projections, fused concat+transpose into output
    gemm_proj_bf16<<<dim3(32, 2, 8), 256>>>(oh, (long)NTOK * 128, h_proj_w, h_proj_b,
                                            out, 0);
    gemm_proj_bf16<<<dim3(32, 2, 8), 256>>>(ol, (long)NTOK * 128, l_proj_w, l_proj_b,
                                            out, 128);
}